// round 12
// baseline (speedup 1.0000x reference)
#include <cuda_runtime.h>
#include <cstdint>
#include <math.h>

#define Bn 4
#define Rn 256
#define En 8192
#define Dn 256
#define NEXPn 8
#define CAPn 1280
#define BUDGETn 7864
#define EG (Bn*En)
#define OFF_REL   65536
#define OFF_MASK  98304
#define OFF_SCORE 131072
#define OFF_TAIL  163840

// ------------- static device scratch (no allocations allowed) ---------------
__device__ float g_ef [EG*Dn];   // edge_feat -> edge_feat2 -> h
__device__ float g_xn [EG*Dn];   // LN outputs (reused)
__device__ float g_tok[EG*Dn];   // token -> routed (reused)
__device__ float g_nodef[Bn*Rn*Dn];
__device__ float g_commf[Bn*Rn*Dn];
__device__ int   g_rel[EG];
__device__ int   g_stats[Bn*10];

// ------------------------------- helpers ------------------------------------
__device__ __forceinline__ float gelu_f(float x){
    return 0.5f * x * (1.0f + erff(x * 0.7071067811865476f));
}
__device__ __forceinline__ uint32_t rotl32(uint32_t x, int d){
    return (x << d) | (x >> (32 - d));
}
// JAX threefry2x32 with key (0, 42): 20 rounds, rot {13,15,26,6,17,29,16,24}
__device__ __forceinline__ uint2 threefry2x32_k42(uint32_t x0, uint32_t x1){
    const uint32_t ks0 = 0u, ks1 = 42u;
    const uint32_t ks2 = ks0 ^ ks1 ^ 0x1BD11BDAu;
    const uint32_t ks[3] = {ks0, ks1, ks2};
    const int rotA[4] = {13,15,26,6};
    const int rotB[4] = {17,29,16,24};
    x0 += ks0; x1 += ks1;
    #pragma unroll
    for (int i = 0; i < 5; i++){
        #pragma unroll
        for (int j = 0; j < 4; j++){
            int rr = (i & 1) ? rotB[j] : rotA[j];
            x0 += x1; x1 = rotl32(x1, rr); x1 ^= x0;
        }
        x0 += ks[(i+1)%3];
        x1 += ks[(i+2)%3] + (uint32_t)(i+1);
    }
    return make_uint2(x0, x1);
}
// JAX random bits, PARTITIONABLE threefry (default since jax 0.4.30):
// counts (hi, lo) = (idx >> 32, idx & 0xffffffff) = (0, idx) for idx < 2^32;
// 32-bit output = out0 ^ out1.
__device__ __forceinline__ uint32_t jax_bits(uint32_t idx){
    uint2 o2 = threefry2x32_k42(0u, idx);
    return o2.x ^ o2.y;
}

// --------- generic fp32 GEMM: C = epi(A[MxK] @ B[KxN] + bias) ---------------
// EPI: 0 = bias only, 1 = gelu(acc+bias), 2 = addsrc + gelu(acc+bias)
template<int EPI>
__global__ void __launch_bounds__(256) gemm_k(
    const float* __restrict__ A, const float* __restrict__ Bm,
    const float* __restrict__ bias, const float* __restrict__ addsrc,
    float* __restrict__ C, int M, int N, int K)
{
    __shared__ float As[16][128];
    __shared__ float Bs[16][128];
    const int bn = blockIdx.x * 128;
    const int bm = blockIdx.y * 128;
    const int t  = threadIdx.x;
    const int tx = t & 15, ty = t >> 4;

    float acc[8][8] = {};

    for (int k0 = 0; k0 < K; k0 += 16){
        #pragma unroll
        for (int i = 0; i < 2; i++){
            int f = t*2 + i;
            int m = f >> 2;
            int kk = (f & 3) * 4;
            float4 v = *reinterpret_cast<const float4*>(A + (size_t)(bm+m)*K + k0 + kk);
            As[kk+0][m] = v.x; As[kk+1][m] = v.y; As[kk+2][m] = v.z; As[kk+3][m] = v.w;
        }
        #pragma unroll
        for (int i = 0; i < 2; i++){
            int f = t*2 + i;
            int kk = f >> 5;
            int n4 = (f & 31) * 4;
            *reinterpret_cast<float4*>(&Bs[kk][n4]) =
                *reinterpret_cast<const float4*>(Bm + (size_t)(k0+kk)*N + bn + n4);
        }
        __syncthreads();
        #pragma unroll
        for (int kk = 0; kk < 16; kk++){
            float a[8], b[8];
            *reinterpret_cast<float4*>(a)   = *reinterpret_cast<const float4*>(&As[kk][ty*8]);
            *reinterpret_cast<float4*>(a+4) = *reinterpret_cast<const float4*>(&As[kk][ty*8+4]);
            *reinterpret_cast<float4*>(b)   = *reinterpret_cast<const float4*>(&Bs[kk][tx*8]);
            *reinterpret_cast<float4*>(b+4) = *reinterpret_cast<const float4*>(&Bs[kk][tx*8+4]);
            #pragma unroll
            for (int i = 0; i < 8; i++)
                #pragma unroll
                for (int j = 0; j < 8; j++)
                    acc[i][j] = fmaf(a[i], b[j], acc[i][j]);
        }
        __syncthreads();
    }
    #pragma unroll
    for (int i = 0; i < 8; i++){
        int row = bm + ty*8 + i;
        #pragma unroll
        for (int j = 0; j < 8; j++){
            int col = bn + tx*8 + j;
            float v = acc[i][j] + bias[col];
            if (EPI == 1) v = gelu_f(v);
            if (EPI == 2) v = addsrc[(size_t)row*N + col] + gelu_f(v);
            C[(size_t)row*N + col] = v;
        }
    }
}

// ---- fused gather GEMM: token = [ef2 | nf[src] | nf[dst] | |cS-cD|] @ Wtok -
__global__ void __launch_bounds__(256) gemm_tok_k(
    const float* __restrict__ ef2, const float* __restrict__ nodef,
    const float* __restrict__ commf, const int* __restrict__ eidx,
    const float* __restrict__ Wtok, const float* __restrict__ bias,
    float* __restrict__ C)
{
    __shared__ float As[16][128];
    __shared__ float Bs[16][128];
    __shared__ int s_s[128], d_s[128];
    const int bn = blockIdx.x * 128;
    const int bm = blockIdx.y * 128;   // 8192 % 128 == 0 -> block stays in one batch
    const int t  = threadIdx.x;
    const int tx = t & 15, ty = t >> 4;
    const int bidx = bm >> 13;
    const int nb   = bidx << 8;        // batch*R

    if (t < 128){
        int ei = (bm & (En-1)) + t;
        s_s[t] = eidx[bidx*2*En + ei];
        d_s[t] = eidx[bidx*2*En + En + ei];
    }
    float acc[8][8] = {};
    __syncthreads();

    for (int k0 = 0; k0 < 1024; k0 += 16){
        const int seg = k0 >> 8;
        const int off = k0 & 255;
        #pragma unroll
        for (int i = 0; i < 2; i++){
            int f = t*2 + i;
            int m = f >> 2;
            int kk = (f & 3) * 4;
            int e = bm + m;
            float4 v;
            if (seg == 0){
                v = *reinterpret_cast<const float4*>(ef2 + (size_t)e*256 + off + kk);
            } else if (seg == 1){
                v = *reinterpret_cast<const float4*>(nodef + (size_t)(nb + s_s[m])*256 + off + kk);
            } else if (seg == 2){
                v = *reinterpret_cast<const float4*>(nodef + (size_t)(nb + d_s[m])*256 + off + kk);
            } else {
                float4 a4 = *reinterpret_cast<const float4*>(commf + (size_t)(nb + s_s[m])*256 + off + kk);
                float4 c4 = *reinterpret_cast<const float4*>(commf + (size_t)(nb + d_s[m])*256 + off + kk);
                v = make_float4(fabsf(a4.x-c4.x), fabsf(a4.y-c4.y),
                                fabsf(a4.z-c4.z), fabsf(a4.w-c4.w));
            }
            As[kk+0][m] = v.x; As[kk+1][m] = v.y; As[kk+2][m] = v.z; As[kk+3][m] = v.w;
        }
        #pragma unroll
        for (int i = 0; i < 2; i++){
            int f = t*2 + i;
            int kk = f >> 5;
            int n4 = (f & 31) * 4;
            *reinterpret_cast<float4*>(&Bs[kk][n4]) =
                *reinterpret_cast<const float4*>(Wtok + (size_t)(k0+kk)*256 + bn + n4);
        }
        __syncthreads();
        #pragma unroll
        for (int kk = 0; kk < 16; kk++){
            float a[8], b[8];
            *reinterpret_cast<float4*>(a)   = *reinterpret_cast<const float4*>(&As[kk][ty*8]);
            *reinterpret_cast<float4*>(a+4) = *reinterpret_cast<const float4*>(&As[kk][ty*8+4]);
            *reinterpret_cast<float4*>(b)   = *reinterpret_cast<const float4*>(&Bs[kk][tx*8]);
            *reinterpret_cast<float4*>(b+4) = *reinterpret_cast<const float4*>(&Bs[kk][tx*8+4]);
            #pragma unroll
            for (int i = 0; i < 8; i++)
                #pragma unroll
                for (int j = 0; j < 8; j++)
                    acc[i][j] = fmaf(a[i], b[j], acc[i][j]);
        }
        __syncthreads();
    }
    #pragma unroll
    for (int i = 0; i < 8; i++){
        int row = bm + ty*8 + i;
        #pragma unroll
        for (int j = 0; j < 8; j++){
            int col = bn + tx*8 + j;
            C[(size_t)row*256 + col] = acc[i][j] + bias[col];
        }
    }
}

// ---------------- LayerNorm over last dim (256), one block per row ----------
__global__ void __launch_bounds__(256) ln_k(
    const float* __restrict__ x, float* __restrict__ y,
    const float* __restrict__ g, const float* __restrict__ bb)
{
    const int row = blockIdx.x, t = threadIdx.x;
    __shared__ float red[8];
    float v = x[(size_t)row*256 + t];
    float s = v;
    #pragma unroll
    for (int o = 16; o; o >>= 1) s += __shfl_xor_sync(0xffffffffu, s, o);
    if ((t & 31) == 0) red[t >> 5] = s;
    __syncthreads();
    float tot = 0.0f;
    #pragma unroll
    for (int i = 0; i < 8; i++) tot += red[i];
    float mu = tot * (1.0f/256.0f);
    float d = v - mu;
    __syncthreads();
    float s2 = d * d;
    #pragma unroll
    for (int o = 16; o; o >>= 1) s2 += __shfl_xor_sync(0xffffffffu, s2, o);
    if ((t & 31) == 0) red[t >> 5] = s2;
    __syncthreads();
    float tot2 = 0.0f;
    #pragma unroll
    for (int i = 0; i < 8; i++) tot2 += red[i];
    float var = tot2 * (1.0f/256.0f);
    y[(size_t)row*256 + t] = d * rsqrtf(var + 1e-5f) * g[t] + bb[t];
}

// ------- logits (warp dot products) + serial Gumbel/argmax on lane 0 --------
__global__ void __launch_bounds__(256) logits2_k(
    const float* __restrict__ routed, const float* __restrict__ hp,
    int* __restrict__ relout)
{
    const int gw = (blockIdx.x * 256 + threadIdx.x) >> 5;   // one warp per edge
    const int lane = threadIdx.x & 31;
    const float* r = routed + (size_t)gw * 256;
    float x[8];
    #pragma unroll
    for (int i = 0; i < 8; i++) x[i] = r[lane + 32*i];
    float myl = 0.0f;
    #pragma unroll
    for (int m = 0; m < 8; m++){
        const float* h = hp + m*256;
        float p = 0.0f;
        #pragma unroll
        for (int i = 0; i < 8; i++) p = fmaf(x[i], h[lane + 32*i], p);
        #pragma unroll
        for (int o = 16; o; o >>= 1) p += __shfl_xor_sync(0xffffffffu, p, o);
        if (lane == m) myl = p;
    }
    // gather all 8 logits to every lane (convergent shuffles)
    float l[8];
    #pragma unroll
    for (int m = 0; m < 8; m++) l[m] = __shfl_sync(0xffffffffu, myl, m);
    if (lane == 0){
        const float lo = 1e-6f;
        const float hi = 1.0f - 1e-6f;
        const float span = hi - lo;
        float best = -INFINITY; int bi = 0;
        #pragma unroll
        for (int m = 0; m < 8; m++){
            uint32_t bits = jax_bits((uint32_t)gw * 8u + (uint32_t)m);
            float f = __uint_as_float((bits >> 9) | 0x3f800000u) - 1.0f;
            float u = fmaxf(lo, __fadd_rn(__fmul_rn(f, span), lo));
            float z = l[m] - logf(-logf(u));
            if (z > best){ best = z; bi = m; }   // strict > => lowest-index ties
        }
        relout[gw] = bi;
    }
}

// ------- routing tail: serial-on-t0 cap/budget/slots, parallel guard/write --
__global__ void __launch_bounds__(256) route2_k(
    const int* __restrict__ relg, const int* __restrict__ eidx,
    float* __restrict__ out, int* __restrict__ stats)
{
    __shared__ unsigned char  rel_s[En];
    __shared__ unsigned char  keep_s[En];
    __shared__ unsigned short slot_s[En];
    __shared__ unsigned char  cov_s[Rn];
    const int b = blockIdx.x;
    const int t = threadIdx.x;
    const int* src = eidx + b*2*En;
    const int* dst = src + En;

    for (int e = t; e < En; e += 256) rel_s[e] = (unsigned char)relg[b*En + e];
    if (t < Rn) cov_s[t] = 0;
    __syncthreads();

    // ---- capacity (serial; scores all 1.0 -> rank within relation by index)
    if (t == 0){
        int cnt[8] = {0,0,0,0,0,0,0,0};
        int kept1 = 0;
        for (int e = 0; e < En; e++){
            int r = rel_s[e];
            int k = (cnt[r] < CAPn) ? 1 : 0;
            cnt[r]++;
            keep_s[e] = (unsigned char)k;
            kept1 += k;
        }
        stats[b*10 + 0] = kept1;                 // for overflow
        #pragma unroll
        for (int m = 0; m < 8; m++) stats[b*10 + 2 + m] = cnt[m];  // for load
    }
    __syncthreads();

    // ---- guard: add every edge touching an uncovered node (best==score==1)
    for (int e = t; e < En; e += 256)
        if (keep_s[e]){ cov_s[src[e]] = 1; cov_s[dst[e]] = 1; }
    __syncthreads();
    for (int e = t; e < En; e += 256)
        if (!cov_s[src[e]] || !cov_s[dst[e]]) keep_s[e] = 1;
    __syncthreads();

    // ---- budget (first BUDGET kept by index) + pack slots (serial)
    if (t == 0){
        int run = 0;
        for (int e = 0; e < En; e++){
            if (keep_s[e]){
                if (run < BUDGETn) run++;
                else keep_s[e] = 0;
            }
        }
        stats[b*10 + 1] = run;                   // Kb (for kept_ratio)
        int ka = 0, da = run;
        for (int e = 0; e < En; e++){
            if (keep_s[e]) slot_s[e] = (unsigned short)(ka++);
            else           slot_s[e] = (unsigned short)(da++);
        }
    }
    __syncthreads();

    // ---- write outputs (parallel)
    for (int e = t; e < En; e += 256){
        int slot = slot_s[e];
        int v = keep_s[e];
        out[b*2*En + slot]           = (float)src[e];
        out[b*2*En + En + slot]      = (float)dst[e];
        out[OFF_REL   + b*En + slot] = v ? (float)rel_s[e] : 0.0f;
        out[OFF_MASK  + b*En + slot] = v ? 1.0f : 0.0f;
        out[OFF_SCORE + b*En + slot] = v ? 1.0f : 0.0f;
    }
}

// ---------------- tail scalars ----------------------------------------------
__global__ void finalize_k(const int* __restrict__ stats, float* __restrict__ out){
    int t = threadIdx.x;
    if (t < 8){
        int s = 0;
        for (int b = 0; b < Bn; b++) s += stats[b*10 + 2 + t];
        out[OFF_TAIL + t] = (float)s / 32768.0f;
    } else if (t == 8){
        int s = 0;
        for (int b = 0; b < Bn; b++) s += stats[b*10 + 1];
        out[OFF_TAIL + 8] = (float)s / 32768.0f;
    } else if (t == 9){
        int s = 0;
        for (int b = 0; b < Bn; b++) s += stats[b*10 + 0];
        out[OFF_TAIL + 9] = 1.0f - (float)s / 32768.0f;
    }
}

// ------------------------------ launch --------------------------------------
extern "C" void kernel_launch(void* const* d_in, const int* in_sizes, int n_in,
                              void* d_out, int out_size)
{
    (void)in_sizes; (void)n_in; (void)out_size;
    const float* node_x  = (const float*)d_in[0];
    const int*   eidx    = (const int*)  d_in[1];
    const float* ebank   = (const float*)d_in[2];
    const float* commctx = (const float*)d_in[3];
    const float* W_node  = (const float*)d_in[4];
    const float* b_node  = (const float*)d_in[5];
    const float* W_edge  = (const float*)d_in[6];
    const float* b_edge  = (const float*)d_in[7];
    const float* W_comm  = (const float*)d_in[8];
    const float* b_comm  = (const float*)d_in[9];
    const float* ln_c_g  = (const float*)d_in[10];
    const float* ln_c_b  = (const float*)d_in[11];
    const float* W_clu   = (const float*)d_in[12];
    const float* b_clu   = (const float*)d_in[13];
    const float* W_tok   = (const float*)d_in[14];
    const float* b_tok   = (const float*)d_in[15];
    const float* W_r1    = (const float*)d_in[16];
    const float* b_r1    = (const float*)d_in[17];
    const float* ln_r_g  = (const float*)d_in[18];
    const float* ln_r_b  = (const float*)d_in[19];
    const float* W_r2    = (const float*)d_in[20];
    const float* b_r2    = (const float*)d_in[21];
    const float* hp      = (const float*)d_in[22];
    float* out = (float*)d_out;

    float *p_ef, *p_xn, *p_tok, *p_nodef, *p_commf;
    int *p_rel, *p_stats;
    cudaGetSymbolAddress((void**)&p_ef,    g_ef);
    cudaGetSymbolAddress((void**)&p_xn,    g_xn);
    cudaGetSymbolAddress((void**)&p_tok,   g_tok);
    cudaGetSymbolAddress((void**)&p_nodef, g_nodef);
    cudaGetSymbolAddress((void**)&p_commf, g_commf);
    cudaGetSymbolAddress((void**)&p_rel,   g_rel);
    cudaGetSymbolAddress((void**)&p_stats, g_stats);

    dim3 blk(256);
    dim3 gSmall(2, 8);     // 1024 x 256
    dim3 gBig(2, 256);     // 32768 x 256

    // node_feat, comm_feat
    gemm_k<0><<<gSmall, blk>>>(node_x,  W_node, b_node, nullptr, p_nodef, 1024, 256, 256);
    gemm_k<0><<<gSmall, blk>>>(commctx, W_comm, b_comm, nullptr, p_commf, 1024, 256, 32);
    // edge_feat
    gemm_k<0><<<gBig, blk>>>(ebank, W_edge, b_edge, nullptr, p_ef, EG, 256, 16);
    // edge_feat2 = edge_feat + gelu(LN(edge_feat) @ W_clu + b_clu)
    ln_k<<<EG, blk>>>(p_ef, p_xn, ln_c_g, ln_c_b);
    gemm_k<2><<<gBig, blk>>>(p_xn, W_clu, b_clu, p_ef, p_ef, EG, 256, 256);
    // token = [ef2 | nf[src] | nf[dst] | |cS-cD|] @ W_tok + b_tok
    gemm_tok_k<<<gBig, blk>>>(p_ef, p_nodef, p_commf, eidx, W_tok, b_tok, p_tok);
    // h = gelu(token @ W_r1 + b_r1)
    gemm_k<1><<<gBig, blk>>>(p_tok, W_r1, b_r1, nullptr, p_ef, EG, 256, 256);
    // h = LN(h)
    ln_k<<<EG, blk>>>(p_ef, p_xn, ln_r_g, ln_r_b);
    // routed = gelu(h @ W_r2 + b_r2)
    gemm_k<1><<<gBig, blk>>>(p_xn, W_r2, b_r2, nullptr, p_tok, EG, 256, 256);
    // relation_id
    logits2_k<<<EG*32/256, blk>>>(p_tok, hp, p_rel);
    // cap / guard / budget / pack + outputs (serial-verified tail)
    route2_k<<<Bn, blk>>>(p_rel, eidx, out, p_stats);
    finalize_k<<<1, 32>>>(p_stats, out);
}

// round 14
// speedup vs baseline: 1.0916x; 1.0916x over previous
#include <cuda_runtime.h>
#include <cstdint>
#include <math.h>

#define Bn 4
#define Rn 256
#define En 8192
#define Dn 256
#define NEXPn 8
#define CAPn 1280
#define BUDGETn 7864
#define EG (Bn*En)
#define OFF_REL   65536
#define OFF_MASK  98304
#define OFF_SCORE 131072
#define OFF_TAIL  163840

typedef unsigned long long u64t;

// ------------- static device scratch (no allocations allowed) ---------------
__device__ float g_ef [EG*Dn];   // edge_feat -> edge_feat2 -> h
__device__ float g_xn [EG*Dn];   // LN outputs (reused)
__device__ float g_tok[EG*Dn];   // token -> routed (reused)
__device__ float g_nodef[Bn*Rn*Dn];
__device__ float g_commf[Bn*Rn*Dn];
__device__ int   g_rel[EG];
__device__ int   g_stats[Bn*10];

// ------------------------------- helpers ------------------------------------
__device__ __forceinline__ float gelu_f(float x){
    return 0.5f * x * (1.0f + erff(x * 0.7071067811865476f));
}
__device__ __forceinline__ uint32_t rotl32(uint32_t x, int d){
    return (x << d) | (x >> (32 - d));
}
// JAX threefry2x32 with key (0, 42)
__device__ __forceinline__ uint2 threefry2x32_k42(uint32_t x0, uint32_t x1){
    const uint32_t ks0 = 0u, ks1 = 42u;
    const uint32_t ks2 = ks0 ^ ks1 ^ 0x1BD11BDAu;
    const uint32_t ks[3] = {ks0, ks1, ks2};
    const int rotA[4] = {13,15,26,6};
    const int rotB[4] = {17,29,16,24};
    x0 += ks0; x1 += ks1;
    #pragma unroll
    for (int i = 0; i < 5; i++){
        #pragma unroll
        for (int j = 0; j < 4; j++){
            int rr = (i & 1) ? rotB[j] : rotA[j];
            x0 += x1; x1 = rotl32(x1, rr); x1 ^= x0;
        }
        x0 += ks[(i+1)%3];
        x1 += ks[(i+2)%3] + (uint32_t)(i+1);
    }
    return make_uint2(x0, x1);
}
// JAX partitionable threefry bits: counts (0, idx), out = out0 ^ out1
__device__ __forceinline__ uint32_t jax_bits(uint32_t idx){
    uint2 o2 = threefry2x32_k42(0u, idx);
    return o2.x ^ o2.y;
}

// ---- packed f32x2 FMA helpers (FFMA2 — PTX-only on sm_103a) ----------------
__device__ __forceinline__ u64t pk2(float lo, float hi){
    u64t r;
    asm("mov.b64 %0, {%1, %2};" : "=l"(r) : "f"(lo), "f"(hi));
    return r;
}
__device__ __forceinline__ void fma2(u64t &d, u64t a, u64t b){
    asm("fma.rn.f32x2 %0, %1, %2, %3;" : "=l"(d) : "l"(a), "l"(b), "l"(d));
}
__device__ __forceinline__ float2 upk2(u64t v){
    float2 f;
    asm("mov.b64 {%0, %1}, %2;" : "=f"(f.x), "=f"(f.y) : "l"(v));
    return f;
}

// --------- generic fp32 GEMM (FFMA2 + double-buffered smem) -----------------
// C = epi(A[MxK] @ B[KxN] + bias); EPI: 0 bias, 1 gelu, 2 addsrc+gelu
template<int EPI>
__global__ void __launch_bounds__(256, 2) gemm_k(
    const float* __restrict__ A, const float* __restrict__ Bm,
    const float* __restrict__ bias, const float* __restrict__ addsrc,
    float* __restrict__ C, int M, int N, int K)
{
    __shared__ float As[2][16][128];
    __shared__ float Bs[2][16][128];
    const int bn = blockIdx.x * 128;
    const int bm = blockIdx.y * 128;
    const int t  = threadIdx.x;
    const int tx = t & 15, ty = t >> 4;
    const int nk = K >> 4;

    u64t acc[8][4];
    #pragma unroll
    for (int i = 0; i < 8; i++)
        #pragma unroll
        for (int j = 0; j < 4; j++) acc[i][j] = 0ull;

    // per-thread global-load coordinates (same as before)
    const int am0 = (t*2)     >> 2, ak0 = ((t*2)     & 3) * 4;
    const int am1 = (t*2 + 1) >> 2, ak1 = ((t*2 + 1) & 3) * 4;
    const int bk0 = (t*2)     >> 5, bn0 = ((t*2)     & 31) * 4;
    const int bk1 = (t*2 + 1) >> 5, bn1 = ((t*2 + 1) & 31) * 4;

    float4 ra0, ra1, rb0, rb1;
    // preload k0 = 0
    ra0 = *reinterpret_cast<const float4*>(A + (size_t)(bm+am0)*K + ak0);
    ra1 = *reinterpret_cast<const float4*>(A + (size_t)(bm+am1)*K + ak1);
    rb0 = *reinterpret_cast<const float4*>(Bm + (size_t)bk0*N + bn + bn0);
    rb1 = *reinterpret_cast<const float4*>(Bm + (size_t)bk1*N + bn + bn1);
    As[0][ak0+0][am0] = ra0.x; As[0][ak0+1][am0] = ra0.y; As[0][ak0+2][am0] = ra0.z; As[0][ak0+3][am0] = ra0.w;
    As[0][ak1+0][am1] = ra1.x; As[0][ak1+1][am1] = ra1.y; As[0][ak1+2][am1] = ra1.z; As[0][ak1+3][am1] = ra1.w;
    *reinterpret_cast<float4*>(&Bs[0][bk0][bn0]) = rb0;
    *reinterpret_cast<float4*>(&Bs[0][bk1][bn1]) = rb1;
    __syncthreads();

    for (int it = 0; it < nk; it++){
        const int cur = it & 1;
        if (it + 1 < nk){
            int k0 = (it+1) << 4;
            ra0 = *reinterpret_cast<const float4*>(A + (size_t)(bm+am0)*K + k0 + ak0);
            ra1 = *reinterpret_cast<const float4*>(A + (size_t)(bm+am1)*K + k0 + ak1);
            rb0 = *reinterpret_cast<const float4*>(Bm + (size_t)(k0+bk0)*N + bn + bn0);
            rb1 = *reinterpret_cast<const float4*>(Bm + (size_t)(k0+bk1)*N + bn + bn1);
        }
        #pragma unroll
        for (int kk = 0; kk < 16; kk++){
            float a[8], b[8];
            *reinterpret_cast<float4*>(a)   = *reinterpret_cast<const float4*>(&As[cur][kk][ty*8]);
            *reinterpret_cast<float4*>(a+4) = *reinterpret_cast<const float4*>(&As[cur][kk][ty*8+4]);
            *reinterpret_cast<float4*>(b)   = *reinterpret_cast<const float4*>(&Bs[cur][kk][tx*8]);
            *reinterpret_cast<float4*>(b+4) = *reinterpret_cast<const float4*>(&Bs[cur][kk][tx*8+4]);
            u64t bp[4];
            #pragma unroll
            for (int j = 0; j < 4; j++) bp[j] = pk2(b[2*j], b[2*j+1]);
            #pragma unroll
            for (int i = 0; i < 8; i++){
                u64t ap = pk2(a[i], a[i]);
                #pragma unroll
                for (int j = 0; j < 4; j++) fma2(acc[i][j], ap, bp[j]);
            }
        }
        if (it + 1 < nk){
            const int nxt = cur ^ 1;
            As[nxt][ak0+0][am0] = ra0.x; As[nxt][ak0+1][am0] = ra0.y; As[nxt][ak0+2][am0] = ra0.z; As[nxt][ak0+3][am0] = ra0.w;
            As[nxt][ak1+0][am1] = ra1.x; As[nxt][ak1+1][am1] = ra1.y; As[nxt][ak1+2][am1] = ra1.z; As[nxt][ak1+3][am1] = ra1.w;
            *reinterpret_cast<float4*>(&Bs[nxt][bk0][bn0]) = rb0;
            *reinterpret_cast<float4*>(&Bs[nxt][bk1][bn1]) = rb1;
        }
        __syncthreads();
    }

    #pragma unroll
    for (int i = 0; i < 8; i++){
        int row = bm + ty*8 + i;
        #pragma unroll
        for (int j = 0; j < 4; j++){
            float2 vv = upk2(acc[i][j]);
            #pragma unroll
            for (int h = 0; h < 2; h++){
                int col = bn + tx*8 + 2*j + h;
                float v = (h ? vv.y : vv.x) + bias[col];
                if (EPI == 1) v = gelu_f(v);
                if (EPI == 2) v = addsrc[(size_t)row*N + col] + gelu_f(v);
                C[(size_t)row*N + col] = v;
            }
        }
    }
}

// ---- fused gather GEMM: token = [ef2 | nf[src] | nf[dst] | |cS-cD|] @ Wtok -
__global__ void __launch_bounds__(256, 2) gemm_tok_k(
    const float* __restrict__ ef2, const float* __restrict__ nodef,
    const float* __restrict__ commf, const int* __restrict__ eidx,
    const float* __restrict__ Wtok, const float* __restrict__ bias,
    float* __restrict__ C)
{
    __shared__ float As[2][16][128];
    __shared__ float Bs[2][16][128];
    __shared__ int s_s[128], d_s[128];
    const int bn = blockIdx.x * 128;
    const int bm = blockIdx.y * 128;   // 8192 % 128 == 0 -> one batch per block
    const int t  = threadIdx.x;
    const int tx = t & 15, ty = t >> 4;
    const int bidx = bm >> 13;
    const int nb   = bidx << 8;        // batch*R

    if (t < 128){
        int ei = (bm & (En-1)) + t;
        s_s[t] = eidx[bidx*2*En + ei];
        d_s[t] = eidx[bidx*2*En + En + ei];
    }
    u64t acc[8][4];
    #pragma unroll
    for (int i = 0; i < 8; i++)
        #pragma unroll
        for (int j = 0; j < 4; j++) acc[i][j] = 0ull;

    const int am0 = (t*2)     >> 2, ak0 = ((t*2)     & 3) * 4;
    const int am1 = (t*2 + 1) >> 2, ak1 = ((t*2 + 1) & 3) * 4;
    const int bk0 = (t*2)     >> 5, bn0 = ((t*2)     & 31) * 4;
    const int bk1 = (t*2 + 1) >> 5, bn1 = ((t*2 + 1) & 31) * 4;
    __syncthreads();

    // gather load for one A slot (row m in tile, k-offset k0+kk..+3)
    auto loadA = [&](int k0, int m, int kk) -> float4 {
        const int seg = k0 >> 8;
        const int off = (k0 & 255) + kk;
        int e = bm + m;
        float4 v;
        if (seg == 0){
            v = *reinterpret_cast<const float4*>(ef2 + (size_t)e*256 + off);
        } else if (seg == 1){
            v = *reinterpret_cast<const float4*>(nodef + (size_t)(nb + s_s[m])*256 + off);
        } else if (seg == 2){
            v = *reinterpret_cast<const float4*>(nodef + (size_t)(nb + d_s[m])*256 + off);
        } else {
            float4 a4 = *reinterpret_cast<const float4*>(commf + (size_t)(nb + s_s[m])*256 + off);
            float4 c4 = *reinterpret_cast<const float4*>(commf + (size_t)(nb + d_s[m])*256 + off);
            v = make_float4(fabsf(a4.x-c4.x), fabsf(a4.y-c4.y),
                            fabsf(a4.z-c4.z), fabsf(a4.w-c4.w));
        }
        return v;
    };

    float4 ra0, ra1, rb0, rb1;
    ra0 = loadA(0, am0, ak0);
    ra1 = loadA(0, am1, ak1);
    rb0 = *reinterpret_cast<const float4*>(Wtok + (size_t)bk0*256 + bn + bn0);
    rb1 = *reinterpret_cast<const float4*>(Wtok + (size_t)bk1*256 + bn + bn1);
    As[0][ak0+0][am0] = ra0.x; As[0][ak0+1][am0] = ra0.y; As[0][ak0+2][am0] = ra0.z; As[0][ak0+3][am0] = ra0.w;
    As[0][ak1+0][am1] = ra1.x; As[0][ak1+1][am1] = ra1.y; As[0][ak1+2][am1] = ra1.z; As[0][ak1+3][am1] = ra1.w;
    *reinterpret_cast<float4*>(&Bs[0][bk0][bn0]) = rb0;
    *reinterpret_cast<float4*>(&Bs[0][bk1][bn1]) = rb1;
    __syncthreads();

    const int nk = 1024 >> 4;   // 64
    for (int it = 0; it < nk; it++){
        const int cur = it & 1;
        if (it + 1 < nk){
            int k0 = (it+1) << 4;
            ra0 = loadA(k0, am0, ak0);
            ra1 = loadA(k0, am1, ak1);
            rb0 = *reinterpret_cast<const float4*>(Wtok + (size_t)(k0+bk0)*256 + bn + bn0);
            rb1 = *reinterpret_cast<const float4*>(Wtok + (size_t)(k0+bk1)*256 + bn + bn1);
        }
        #pragma unroll
        for (int kk = 0; kk < 16; kk++){
            float a[8], b[8];
            *reinterpret_cast<float4*>(a)   = *reinterpret_cast<const float4*>(&As[cur][kk][ty*8]);
            *reinterpret_cast<float4*>(a+4) = *reinterpret_cast<const float4*>(&As[cur][kk][ty*8+4]);
            *reinterpret_cast<float4*>(b)   = *reinterpret_cast<const float4*>(&Bs[cur][kk][tx*8]);
            *reinterpret_cast<float4*>(b+4) = *reinterpret_cast<const float4*>(&Bs[cur][kk][tx*8+4]);
            u64t bp[4];
            #pragma unroll
            for (int j = 0; j < 4; j++) bp[j] = pk2(b[2*j], b[2*j+1]);
            #pragma unroll
            for (int i = 0; i < 8; i++){
                u64t ap = pk2(a[i], a[i]);
                #pragma unroll
                for (int j = 0; j < 4; j++) fma2(acc[i][j], ap, bp[j]);
            }
        }
        if (it + 1 < nk){
            const int nxt = cur ^ 1;
            As[nxt][ak0+0][am0] = ra0.x; As[nxt][ak0+1][am0] = ra0.y; As[nxt][ak0+2][am0] = ra0.z; As[nxt][ak0+3][am0] = ra0.w;
            As[nxt][ak1+0][am1] = ra1.x; As[nxt][ak1+1][am1] = ra1.y; As[nxt][ak1+2][am1] = ra1.z; As[nxt][ak1+3][am1] = ra1.w;
            *reinterpret_cast<float4*>(&Bs[nxt][bk0][bn0]) = rb0;
            *reinterpret_cast<float4*>(&Bs[nxt][bk1][bn1]) = rb1;
        }
        __syncthreads();
    }

    #pragma unroll
    for (int i = 0; i < 8; i++){
        int row = bm + ty*8 + i;
        #pragma unroll
        for (int j = 0; j < 4; j++){
            float2 vv = upk2(acc[i][j]);
            int col = bn + tx*8 + 2*j;
            C[(size_t)row*256 + col]     = vv.x + bias[col];
            C[(size_t)row*256 + col + 1] = vv.y + bias[col + 1];
        }
    }
}

// ---------------- LayerNorm over last dim (256), one block per row ----------
__global__ void __launch_bounds__(256) ln_k(
    const float* __restrict__ x, float* __restrict__ y,
    const float* __restrict__ g, const float* __restrict__ bb)
{
    const int row = blockIdx.x, t = threadIdx.x;
    __shared__ float red[8];
    float v = x[(size_t)row*256 + t];
    float s = v;
    #pragma unroll
    for (int o = 16; o; o >>= 1) s += __shfl_xor_sync(0xffffffffu, s, o);
    if ((t & 31) == 0) red[t >> 5] = s;
    __syncthreads();
    float tot = 0.0f;
    #pragma unroll
    for (int i = 0; i < 8; i++) tot += red[i];
    float mu = tot * (1.0f/256.0f);
    float d = v - mu;
    __syncthreads();
    float s2 = d * d;
    #pragma unroll
    for (int o = 16; o; o >>= 1) s2 += __shfl_xor_sync(0xffffffffu, s2, o);
    if ((t & 31) == 0) red[t >> 5] = s2;
    __syncthreads();
    float tot2 = 0.0f;
    #pragma unroll
    for (int i = 0; i < 8; i++) tot2 += red[i];
    float var = tot2 * (1.0f/256.0f);
    y[(size_t)row*256 + t] = d * rsqrtf(var + 1e-5f) * g[t] + bb[t];
}

// ------- logits (warp dot products) + serial Gumbel/argmax on lane 0 --------
__global__ void __launch_bounds__(256) logits2_k(
    const float* __restrict__ routed, const float* __restrict__ hp,
    int* __restrict__ relout)
{
    const int gw = (blockIdx.x * 256 + threadIdx.x) >> 5;   // one warp per edge
    const int lane = threadIdx.x & 31;
    const float* r = routed + (size_t)gw * 256;
    float x[8];
    #pragma unroll
    for (int i = 0; i < 8; i++) x[i] = r[lane + 32*i];
    float myl = 0.0f;
    #pragma unroll
    for (int m = 0; m < 8; m++){
        const float* h = hp + m*256;
        float p = 0.0f;
        #pragma unroll
        for (int i = 0; i < 8; i++) p = fmaf(x[i], h[lane + 32*i], p);
        #pragma unroll
        for (int o = 16; o; o >>= 1) p += __shfl_xor_sync(0xffffffffu, p, o);
        if (lane == m) myl = p;
    }
    float l[8];
    #pragma unroll
    for (int m = 0; m < 8; m++) l[m] = __shfl_sync(0xffffffffu, myl, m);
    if (lane == 0){
        const float lo = 1e-6f;
        const float hi = 1.0f - 1e-6f;
        const float span = hi - lo;
        float best = -INFINITY; int bi = 0;
        #pragma unroll
        for (int m = 0; m < 8; m++){
            uint32_t bits = jax_bits((uint32_t)gw * 8u + (uint32_t)m);
            float f = __uint_as_float((bits >> 9) | 0x3f800000u) - 1.0f;
            float u = fmaxf(lo, __fadd_rn(__fmul_rn(f, span), lo));
            float z = l[m] - logf(-logf(u));
            if (z > best){ best = z; bi = m; }   // strict > => lowest-index ties
        }
        relout[gw] = bi;
    }
}

// ------- routing tail: serial-on-t0 cap/budget/slots, parallel guard/write --
__global__ void __launch_bounds__(256) route2_k(
    const int* __restrict__ relg, const int* __restrict__ eidx,
    float* __restrict__ out, int* __restrict__ stats)
{
    __shared__ unsigned char  rel_s[En];
    __shared__ unsigned char  keep_s[En];
    __shared__ unsigned short slot_s[En];
    __shared__ unsigned char  cov_s[Rn];
    const int b = blockIdx.x;
    const int t = threadIdx.x;
    const int* src = eidx + b*2*En;
    const int* dst = src + En;

    for (int e = t; e < En; e += 256) rel_s[e] = (unsigned char)relg[b*En + e];
    if (t < Rn) cov_s[t] = 0;
    __syncthreads();

    // ---- capacity (serial; scores all 1.0 -> rank within relation by index)
    if (t == 0){
        int cnt[8] = {0,0,0,0,0,0,0,0};
        int kept1 = 0;
        for (int e = 0; e < En; e++){
            int r = rel_s[e];
            int k = (cnt[r] < CAPn) ? 1 : 0;
            cnt[r]++;
            keep_s[e] = (unsigned char)k;
            kept1 += k;
        }
        stats[b*10 + 0] = kept1;                 // for overflow
        #pragma unroll
        for (int m = 0; m < 8; m++) stats[b*10 + 2 + m] = cnt[m];  // for load
    }
    __syncthreads();

    // ---- guard: add every edge touching an uncovered node (best==score==1)
    for (int e = t; e < En; e += 256)
        if (keep_s[e]){ cov_s[src[e]] = 1; cov_s[dst[e]] = 1; }
    __syncthreads();
    for (int e = t; e < En; e += 256)
        if (!cov_s[src[e]] || !cov_s[dst[e]]) keep_s[e] = 1;
    __syncthreads();

    // ---- budget (first BUDGET kept by index) + pack slots (serial)
    if (t == 0){
        int run = 0;
        for (int e = 0; e < En; e++){
            if (keep_s[e]){
                if (run < BUDGETn) run++;
                else keep_s[e] = 0;
            }
        }
        stats[b*10 + 1] = run;                   // Kb (for kept_ratio)
        int ka = 0, da = run;
        for (int e = 0; e < En; e++){
            if (keep_s[e]) slot_s[e] = (unsigned short)(ka++);
            else           slot_s[e] = (unsigned short)(da++);
        }
    }
    __syncthreads();

    // ---- write outputs (parallel)
    for (int e = t; e < En; e += 256){
        int slot = slot_s[e];
        int v = keep_s[e];
        out[b*2*En + slot]           = (float)src[e];
        out[b*2*En + En + slot]      = (float)dst[e];
        out[OFF_REL   + b*En + slot] = v ? (float)rel_s[e] : 0.0f;
        out[OFF_MASK  + b*En + slot] = v ? 1.0f : 0.0f;
        out[OFF_SCORE + b*En + slot] = v ? 1.0f : 0.0f;
    }
}

// ---------------- tail scalars ----------------------------------------------
__global__ void finalize_k(const int* __restrict__ stats, float* __restrict__ out){
    int t = threadIdx.x;
    if (t < 8){
        int s = 0;
        for (int b = 0; b < Bn; b++) s += stats[b*10 + 2 + t];
        out[OFF_TAIL + t] = (float)s / 32768.0f;
    } else if (t == 8){
        int s = 0;
        for (int b = 0; b < Bn; b++) s += stats[b*10 + 1];
        out[OFF_TAIL + 8] = (float)s / 32768.0f;
    } else if (t == 9){
        int s = 0;
        for (int b = 0; b < Bn; b++) s += stats[b*10 + 0];
        out[OFF_TAIL + 9] = 1.0f - (float)s / 32768.0f;
    }
}

// ------------------------------ launch --------------------------------------
extern "C" void kernel_launch(void* const* d_in, const int* in_sizes, int n_in,
                              void* d_out, int out_size)
{
    (void)in_sizes; (void)n_in; (void)out_size;
    const float* node_x  = (const float*)d_in[0];
    const int*   eidx    = (const int*)  d_in[1];
    const float* ebank   = (const float*)d_in[2];
    const float* commctx = (const float*)d_in[3];
    const float* W_node  = (const float*)d_in[4];
    const float* b_node  = (const float*)d_in[5];
    const float* W_edge  = (const float*)d_in[6];
    const float* b_edge  = (const float*)d_in[7];
    const float* W_comm  = (const float*)d_in[8];
    const float* b_comm  = (const float*)d_in[9];
    const float* ln_c_g  = (const float*)d_in[10];
    const float* ln_c_b  = (const float*)d_in[11];
    const float* W_clu   = (const float*)d_in[12];
    const float* b_clu   = (const float*)d_in[13];
    const float* W_tok   = (const float*)d_in[14];
    const float* b_tok   = (const float*)d_in[15];
    const float* W_r1    = (const float*)d_in[16];
    const float* b_r1    = (const float*)d_in[17];
    const float* ln_r_g  = (const float*)d_in[18];
    const float* ln_r_b  = (const float*)d_in[19];
    const float* W_r2    = (const float*)d_in[20];
    const float* b_r2    = (const float*)d_in[21];
    const float* hp      = (const float*)d_in[22];
    float* out = (float*)d_out;

    float *p_ef, *p_xn, *p_tok, *p_nodef, *p_commf;
    int *p_rel, *p_stats;
    cudaGetSymbolAddress((void**)&p_ef,    g_ef);
    cudaGetSymbolAddress((void**)&p_xn,    g_xn);
    cudaGetSymbolAddress((void**)&p_tok,   g_tok);
    cudaGetSymbolAddress((void**)&p_nodef, g_nodef);
    cudaGetSymbolAddress((void**)&p_commf, g_commf);
    cudaGetSymbolAddress((void**)&p_rel,   g_rel);
    cudaGetSymbolAddress((void**)&p_stats, g_stats);

    dim3 blk(256);
    dim3 gSmall(2, 8);     // 1024 x 256
    dim3 gBig(2, 256);     // 32768 x 256

    // node_feat, comm_feat
    gemm_k<0><<<gSmall, blk>>>(node_x,  W_node, b_node, nullptr, p_nodef, 1024, 256, 256);
    gemm_k<0><<<gSmall, blk>>>(commctx, W_comm, b_comm, nullptr, p_commf, 1024, 256, 32);
    // edge_feat
    gemm_k<0><<<gBig, blk>>>(ebank, W_edge, b_edge, nullptr, p_ef, EG, 256, 16);
    // edge_feat2 = edge_feat + gelu(LN(edge_feat) @ W_clu + b_clu)
    ln_k<<<EG, blk>>>(p_ef, p_xn, ln_c_g, ln_c_b);
    gemm_k<2><<<gBig, blk>>>(p_xn, W_clu, b_clu, p_ef, p_ef, EG, 256, 256);
    // token = [ef2 | nf[src] | nf[dst] | |cS-cD|] @ W_tok + b_tok
    gemm_tok_k<<<gBig, blk>>>(p_ef, p_nodef, p_commf, eidx, W_tok, b_tok, p_tok);
    // h = gelu(token @ W_r1 + b_r1)
    gemm_k<1><<<gBig, blk>>>(p_tok, W_r1, b_r1, nullptr, p_ef, EG, 256, 256);
    // h = LN(h)
    ln_k<<<EG, blk>>>(p_ef, p_xn, ln_r_g, ln_r_b);
    // routed = gelu(h @ W_r2 + b_r2)
    gemm_k<1><<<gBig, blk>>>(p_xn, W_r2, b_r2, nullptr, p_tok, EG, 256, 256);
    // relation_id
    logits2_k<<<EG*32/256, blk>>>(p_tok, hp, p_rel);
    // cap / guard / budget / pack + outputs
    route2_k<<<Bn, blk>>>(p_rel, eidx, out, p_stats);
    finalize_k<<<1, 32>>>(p_stats, out);
}

// round 16
// speedup vs baseline: 1.1737x; 1.0752x over previous
#include <cuda_runtime.h>
#include <cstdint>
#include <math.h>

#define Bn 4
#define Rn 256
#define En 8192
#define Dn 256
#define NEXPn 8
#define CAPn 1280
#define BUDGETn 7864
#define EG (Bn*En)
#define OFF_REL   65536
#define OFF_MASK  98304
#define OFF_SCORE 131072
#define OFF_TAIL  163840

typedef unsigned long long u64t;

// ------------- static device scratch (no allocations allowed) ---------------
__device__ float g_ef [EG*Dn];   // edge_feat -> edge_feat2 -> h
__device__ float g_xn [EG*Dn];   // LN outputs (reused)
__device__ float g_tok[EG*Dn];   // token -> routed (reused)
__device__ float g_nodef[Bn*Rn*Dn];
__device__ float g_commf[Bn*Rn*Dn];
__device__ float g_p1[Bn*Rn*Dn];     // nodef @ W_tok[256:512]
__device__ float g_p2[Bn*Rn*Dn];     // nodef @ W_tok[512:768]
__device__ float g_zerob[Dn];        // zero bias (zero-initialized)
__device__ int   g_rel[EG];
__device__ int   g_stats[Bn*10];

// ------------------------------- helpers ------------------------------------
__device__ __forceinline__ float gelu_f(float x){
    return 0.5f * x * (1.0f + erff(x * 0.7071067811865476f));
}
__device__ __forceinline__ uint32_t rotl32(uint32_t x, int d){
    return (x << d) | (x >> (32 - d));
}
// JAX threefry2x32 with key (0, 42)
__device__ __forceinline__ uint2 threefry2x32_k42(uint32_t x0, uint32_t x1){
    const uint32_t ks0 = 0u, ks1 = 42u;
    const uint32_t ks2 = ks0 ^ ks1 ^ 0x1BD11BDAu;
    const uint32_t ks[3] = {ks0, ks1, ks2};
    const int rotA[4] = {13,15,26,6};
    const int rotB[4] = {17,29,16,24};
    x0 += ks0; x1 += ks1;
    #pragma unroll
    for (int i = 0; i < 5; i++){
        #pragma unroll
        for (int j = 0; j < 4; j++){
            int rr = (i & 1) ? rotB[j] : rotA[j];
            x0 += x1; x1 = rotl32(x1, rr); x1 ^= x0;
        }
        x0 += ks[(i+1)%3];
        x1 += ks[(i+2)%3] + (uint32_t)(i+1);
    }
    return make_uint2(x0, x1);
}
// JAX partitionable threefry bits: counts (0, idx), out = out0 ^ out1
__device__ __forceinline__ uint32_t jax_bits(uint32_t idx){
    uint2 o2 = threefry2x32_k42(0u, idx);
    return o2.x ^ o2.y;
}

// ---- packed f32x2 FMA helpers (FFMA2 — PTX-only on sm_103a) ----------------
__device__ __forceinline__ u64t pk2(float lo, float hi){
    u64t r;
    asm("mov.b64 %0, {%1, %2};" : "=l"(r) : "f"(lo), "f"(hi));
    return r;
}
__device__ __forceinline__ void fma2(u64t &d, u64t a, u64t b){
    asm("fma.rn.f32x2 %0, %1, %2, %3;" : "=l"(d) : "l"(a), "l"(b), "l"(d));
}
__device__ __forceinline__ float2 upk2(u64t v){
    float2 f;
    asm("mov.b64 {%0, %1}, %2;" : "=f"(f.x), "=f"(f.y) : "l"(v));
    return f;
}

// --------- generic fp32 GEMM (FFMA2 + double-buffered smem) -----------------
// C = epi(A[MxK] @ B[KxN] + bias); EPI: 0 bias, 1 gelu, 2 addsrc+gelu
template<int EPI>
__global__ void __launch_bounds__(256, 2) gemm_k(
    const float* __restrict__ A, const float* __restrict__ Bm,
    const float* __restrict__ bias, const float* __restrict__ addsrc,
    float* __restrict__ C, int M, int N, int K)
{
    __shared__ float As[2][16][128];
    __shared__ float Bs[2][16][128];
    const int bn = blockIdx.x * 128;
    const int bm = blockIdx.y * 128;
    const int t  = threadIdx.x;
    const int tx = t & 15, ty = t >> 4;
    const int nk = K >> 4;

    u64t acc[8][4];
    #pragma unroll
    for (int i = 0; i < 8; i++)
        #pragma unroll
        for (int j = 0; j < 4; j++) acc[i][j] = 0ull;

    const int am0 = (t*2)     >> 2, ak0 = ((t*2)     & 3) * 4;
    const int am1 = (t*2 + 1) >> 2, ak1 = ((t*2 + 1) & 3) * 4;
    const int bk0 = (t*2)     >> 5, bn0 = ((t*2)     & 31) * 4;
    const int bk1 = (t*2 + 1) >> 5, bn1 = ((t*2 + 1) & 31) * 4;

    float4 ra0, ra1, rb0, rb1;
    ra0 = *reinterpret_cast<const float4*>(A + (size_t)(bm+am0)*K + ak0);
    ra1 = *reinterpret_cast<const float4*>(A + (size_t)(bm+am1)*K + ak1);
    rb0 = *reinterpret_cast<const float4*>(Bm + (size_t)bk0*N + bn + bn0);
    rb1 = *reinterpret_cast<const float4*>(Bm + (size_t)bk1*N + bn + bn1);
    As[0][ak0+0][am0] = ra0.x; As[0][ak0+1][am0] = ra0.y; As[0][ak0+2][am0] = ra0.z; As[0][ak0+3][am0] = ra0.w;
    As[0][ak1+0][am1] = ra1.x; As[0][ak1+1][am1] = ra1.y; As[0][ak1+2][am1] = ra1.z; As[0][ak1+3][am1] = ra1.w;
    *reinterpret_cast<float4*>(&Bs[0][bk0][bn0]) = rb0;
    *reinterpret_cast<float4*>(&Bs[0][bk1][bn1]) = rb1;
    __syncthreads();

    for (int it = 0; it < nk; it++){
        const int cur = it & 1;
        if (it + 1 < nk){
            int k0 = (it+1) << 4;
            ra0 = *reinterpret_cast<const float4*>(A + (size_t)(bm+am0)*K + k0 + ak0);
            ra1 = *reinterpret_cast<const float4*>(A + (size_t)(bm+am1)*K + k0 + ak1);
            rb0 = *reinterpret_cast<const float4*>(Bm + (size_t)(k0+bk0)*N + bn + bn0);
            rb1 = *reinterpret_cast<const float4*>(Bm + (size_t)(k0+bk1)*N + bn + bn1);
        }
        #pragma unroll
        for (int kk = 0; kk < 16; kk++){
            float a[8], b[8];
            *reinterpret_cast<float4*>(a)   = *reinterpret_cast<const float4*>(&As[cur][kk][ty*8]);
            *reinterpret_cast<float4*>(a+4) = *reinterpret_cast<const float4*>(&As[cur][kk][ty*8+4]);
            *reinterpret_cast<float4*>(b)   = *reinterpret_cast<const float4*>(&Bs[cur][kk][tx*8]);
            *reinterpret_cast<float4*>(b+4) = *reinterpret_cast<const float4*>(&Bs[cur][kk][tx*8+4]);
            u64t bp[4];
            #pragma unroll
            for (int j = 0; j < 4; j++) bp[j] = pk2(b[2*j], b[2*j+1]);
            #pragma unroll
            for (int i = 0; i < 8; i++){
                u64t ap = pk2(a[i], a[i]);
                #pragma unroll
                for (int j = 0; j < 4; j++) fma2(acc[i][j], ap, bp[j]);
            }
        }
        if (it + 1 < nk){
            const int nxt = cur ^ 1;
            As[nxt][ak0+0][am0] = ra0.x; As[nxt][ak0+1][am0] = ra0.y; As[nxt][ak0+2][am0] = ra0.z; As[nxt][ak0+3][am0] = ra0.w;
            As[nxt][ak1+0][am1] = ra1.x; As[nxt][ak1+1][am1] = ra1.y; As[nxt][ak1+2][am1] = ra1.z; As[nxt][ak1+3][am1] = ra1.w;
            *reinterpret_cast<float4*>(&Bs[nxt][bk0][bn0]) = rb0;
            *reinterpret_cast<float4*>(&Bs[nxt][bk1][bn1]) = rb1;
        }
        __syncthreads();
    }

    #pragma unroll
    for (int i = 0; i < 8; i++){
        int row = bm + ty*8 + i;
        #pragma unroll
        for (int j = 0; j < 4; j++){
            float2 vv = upk2(acc[i][j]);
            #pragma unroll
            for (int h = 0; h < 2; h++){
                int col = bn + tx*8 + 2*j + h;
                float v = (h ? vv.y : vv.x) + bias[col];
                if (EPI == 1) v = gelu_f(v);
                if (EPI == 2) v = addsrc[(size_t)row*N + col] + gelu_f(v);
                C[(size_t)row*N + col] = v;
            }
        }
    }
}

// ---- factored token GEMM (K=512): token = [ef2 | |cS-cD|] @ W_tok[{0:256,768:1024}]
//      + P1[src] + P2[dst] + bias       (P1/P2 = nodef @ W_tok[256:512 / 512:768])
__global__ void __launch_bounds__(256, 2) gemm_tok2_k(
    const float* __restrict__ ef2, const float* __restrict__ commf,
    const float* __restrict__ P1, const float* __restrict__ P2,
    const int* __restrict__ eidx,
    const float* __restrict__ Wtok, const float* __restrict__ bias,
    float* __restrict__ C)
{
    __shared__ float As[2][16][128];
    __shared__ float Bs[2][16][128];
    __shared__ int s_s[128], d_s[128];
    const int bn = blockIdx.x * 128;
    const int bm = blockIdx.y * 128;   // 8192 % 128 == 0 -> one batch per block
    const int t  = threadIdx.x;
    const int tx = t & 15, ty = t >> 4;
    const int bidx = bm >> 13;
    const int nb   = bidx << 8;        // batch*R

    if (t < 128){
        int ei = (bm & (En-1)) + t;
        s_s[t] = eidx[bidx*2*En + ei];
        d_s[t] = eidx[bidx*2*En + En + ei];
    }
    u64t acc[8][4];
    #pragma unroll
    for (int i = 0; i < 8; i++)
        #pragma unroll
        for (int j = 0; j < 4; j++) acc[i][j] = 0ull;

    const int am0 = (t*2)     >> 2, ak0 = ((t*2)     & 3) * 4;
    const int am1 = (t*2 + 1) >> 2, ak1 = ((t*2 + 1) & 3) * 4;
    const int bk0 = (t*2)     >> 5, bn0 = ((t*2)     & 31) * 4;
    const int bk1 = (t*2 + 1) >> 5, bn1 = ((t*2 + 1) & 31) * 4;
    __syncthreads();

    // A slot: k in [0,256) -> ef2 row; k in [256,512) -> |comm_s - comm_d|
    auto loadA = [&](int k0, int m, int kk) -> float4 {
        int e = bm + m;
        if (k0 < 256){
            return *reinterpret_cast<const float4*>(ef2 + (size_t)e*256 + k0 + kk);
        } else {
            int off = k0 - 256 + kk;
            float4 a4 = *reinterpret_cast<const float4*>(commf + (size_t)(nb + s_s[m])*256 + off);
            float4 c4 = *reinterpret_cast<const float4*>(commf + (size_t)(nb + d_s[m])*256 + off);
            return make_float4(fabsf(a4.x-c4.x), fabsf(a4.y-c4.y),
                               fabsf(a4.z-c4.z), fabsf(a4.w-c4.w));
        }
    };
    // B row: k in [0,256) -> W rows 0..255 (edge), k in [256,512) -> rows 768..1023 (comm)
    auto wrow = [&](int k) -> size_t {
        return (size_t)(k < 256 ? k : k + 512) * 256;
    };

    float4 ra0, ra1, rb0, rb1;
    ra0 = loadA(0, am0, ak0);
    ra1 = loadA(0, am1, ak1);
    rb0 = *reinterpret_cast<const float4*>(Wtok + wrow(bk0) + bn + bn0);
    rb1 = *reinterpret_cast<const float4*>(Wtok + wrow(bk1) + bn + bn1);
    As[0][ak0+0][am0] = ra0.x; As[0][ak0+1][am0] = ra0.y; As[0][ak0+2][am0] = ra0.z; As[0][ak0+3][am0] = ra0.w;
    As[0][ak1+0][am1] = ra1.x; As[0][ak1+1][am1] = ra1.y; As[0][ak1+2][am1] = ra1.z; As[0][ak1+3][am1] = ra1.w;
    *reinterpret_cast<float4*>(&Bs[0][bk0][bn0]) = rb0;
    *reinterpret_cast<float4*>(&Bs[0][bk1][bn1]) = rb1;
    __syncthreads();

    const int nk = 512 >> 4;   // 32
    for (int it = 0; it < nk; it++){
        const int cur = it & 1;
        if (it + 1 < nk){
            int k0 = (it+1) << 4;
            ra0 = loadA(k0, am0, ak0);
            ra1 = loadA(k0, am1, ak1);
            rb0 = *reinterpret_cast<const float4*>(Wtok + wrow(k0+bk0) + bn + bn0);
            rb1 = *reinterpret_cast<const float4*>(Wtok + wrow(k0+bk1) + bn + bn1);
        }
        #pragma unroll
        for (int kk = 0; kk < 16; kk++){
            float a[8], b[8];
            *reinterpret_cast<float4*>(a)   = *reinterpret_cast<const float4*>(&As[cur][kk][ty*8]);
            *reinterpret_cast<float4*>(a+4) = *reinterpret_cast<const float4*>(&As[cur][kk][ty*8+4]);
            *reinterpret_cast<float4*>(b)   = *reinterpret_cast<const float4*>(&Bs[cur][kk][tx*8]);
            *reinterpret_cast<float4*>(b+4) = *reinterpret_cast<const float4*>(&Bs[cur][kk][tx*8+4]);
            u64t bp[4];
            #pragma unroll
            for (int j = 0; j < 4; j++) bp[j] = pk2(b[2*j], b[2*j+1]);
            #pragma unroll
            for (int i = 0; i < 8; i++){
                u64t ap = pk2(a[i], a[i]);
                #pragma unroll
                for (int j = 0; j < 4; j++) fma2(acc[i][j], ap, bp[j]);
            }
        }
        if (it + 1 < nk){
            const int nxt = cur ^ 1;
            As[nxt][ak0+0][am0] = ra0.x; As[nxt][ak0+1][am0] = ra0.y; As[nxt][ak0+2][am0] = ra0.z; As[nxt][ak0+3][am0] = ra0.w;
            As[nxt][ak1+0][am1] = ra1.x; As[nxt][ak1+1][am1] = ra1.y; As[nxt][ak1+2][am1] = ra1.z; As[nxt][ak1+3][am1] = ra1.w;
            *reinterpret_cast<float4*>(&Bs[nxt][bk0][bn0]) = rb0;
            *reinterpret_cast<float4*>(&Bs[nxt][bk1][bn1]) = rb1;
        }
        __syncthreads();
    }

    #pragma unroll
    for (int i = 0; i < 8; i++){
        int mrow = ty*8 + i;
        int row = bm + mrow;
        const float* p1r = P1 + (size_t)(nb + s_s[mrow])*256;
        const float* p2r = P2 + (size_t)(nb + d_s[mrow])*256;
        #pragma unroll
        for (int j = 0; j < 4; j++){
            float2 vv = upk2(acc[i][j]);
            int col = bn + tx*8 + 2*j;
            float2 q1 = *reinterpret_cast<const float2*>(p1r + col);
            float2 q2 = *reinterpret_cast<const float2*>(p2r + col);
            C[(size_t)row*256 + col]     = vv.x + bias[col]     + q1.x + q2.x;
            C[(size_t)row*256 + col + 1] = vv.y + bias[col + 1] + q1.y + q2.y;
        }
    }
}

// ---------------- LayerNorm over last dim (256), one block per row ----------
__global__ void __launch_bounds__(256) ln_k(
    const float* __restrict__ x, float* __restrict__ y,
    const float* __restrict__ g, const float* __restrict__ bb)
{
    const int row = blockIdx.x, t = threadIdx.x;
    __shared__ float red[8];
    float v = x[(size_t)row*256 + t];
    float s = v;
    #pragma unroll
    for (int o = 16; o; o >>= 1) s += __shfl_xor_sync(0xffffffffu, s, o);
    if ((t & 31) == 0) red[t >> 5] = s;
    __syncthreads();
    float tot = 0.0f;
    #pragma unroll
    for (int i = 0; i < 8; i++) tot += red[i];
    float mu = tot * (1.0f/256.0f);
    float d = v - mu;
    __syncthreads();
    float s2 = d * d;
    #pragma unroll
    for (int o = 16; o; o >>= 1) s2 += __shfl_xor_sync(0xffffffffu, s2, o);
    if ((t & 31) == 0) red[t >> 5] = s2;
    __syncthreads();
    float tot2 = 0.0f;
    #pragma unroll
    for (int i = 0; i < 8; i++) tot2 += red[i];
    float var = tot2 * (1.0f/256.0f);
    y[(size_t)row*256 + t] = d * rsqrtf(var + 1e-5f) * g[t] + bb[t];
}

// ------- logits (warp dot products) + serial Gumbel/argmax on lane 0 --------
__global__ void __launch_bounds__(256) logits2_k(
    const float* __restrict__ routed, const float* __restrict__ hp,
    int* __restrict__ relout)
{
    const int gw = (blockIdx.x * 256 + threadIdx.x) >> 5;   // one warp per edge
    const int lane = threadIdx.x & 31;
    const float* r = routed + (size_t)gw * 256;
    float x[8];
    #pragma unroll
    for (int i = 0; i < 8; i++) x[i] = r[lane + 32*i];
    float myl = 0.0f;
    #pragma unroll
    for (int m = 0; m < 8; m++){
        const float* h = hp + m*256;
        float p = 0.0f;
        #pragma unroll
        for (int i = 0; i < 8; i++) p = fmaf(x[i], h[lane + 32*i], p);
        #pragma unroll
        for (int o = 16; o; o >>= 1) p += __shfl_xor_sync(0xffffffffu, p, o);
        if (lane == m) myl = p;
    }
    float l[8];
    #pragma unroll
    for (int m = 0; m < 8; m++) l[m] = __shfl_sync(0xffffffffu, myl, m);
    if (lane == 0){
        const float lo = 1e-6f;
        const float hi = 1.0f - 1e-6f;
        const float span = hi - lo;
        float best = -INFINITY; int bi = 0;
        #pragma unroll
        for (int m = 0; m < 8; m++){
            uint32_t bits = jax_bits((uint32_t)gw * 8u + (uint32_t)m);
            float f = __uint_as_float((bits >> 9) | 0x3f800000u) - 1.0f;
            float u = fmaxf(lo, __fadd_rn(__fmul_rn(f, span), lo));
            float z = l[m] - logf(-logf(u));
            if (z > best){ best = z; bi = m; }   // strict > => lowest-index ties
        }
        relout[gw] = bi;
    }
}

// ------- routing tail: serial-on-t0 cap/budget/slots, parallel guard/write --
__global__ void __launch_bounds__(256) route2_k(
    const int* __restrict__ relg, const int* __restrict__ eidx,
    float* __restrict__ out, int* __restrict__ stats)
{
    __shared__ unsigned char  rel_s[En];
    __shared__ unsigned char  keep_s[En];
    __shared__ unsigned short slot_s[En];
    __shared__ unsigned char  cov_s[Rn];
    const int b = blockIdx.x;
    const int t = threadIdx.x;
    const int* src = eidx + b*2*En;
    const int* dst = src + En;

    for (int e = t; e < En; e += 256) rel_s[e] = (unsigned char)relg[b*En + e];
    if (t < Rn) cov_s[t] = 0;
    __syncthreads();

    // ---- capacity (serial; scores all 1.0 -> rank within relation by index)
    if (t == 0){
        int cnt[8] = {0,0,0,0,0,0,0,0};
        int kept1 = 0;
        for (int e = 0; e < En; e++){
            int r = rel_s[e];
            int k = (cnt[r] < CAPn) ? 1 : 0;
            cnt[r]++;
            keep_s[e] = (unsigned char)k;
            kept1 += k;
        }
        stats[b*10 + 0] = kept1;                 // for overflow
        #pragma unroll
        for (int m = 0; m < 8; m++) stats[b*10 + 2 + m] = cnt[m];  // for load
    }
    __syncthreads();

    // ---- guard: add every edge touching an uncovered node (best==score==1)
    for (int e = t; e < En; e += 256)
        if (keep_s[e]){ cov_s[src[e]] = 1; cov_s[dst[e]] = 1; }
    __syncthreads();
    for (int e = t; e < En; e += 256)
        if (!cov_s[src[e]] || !cov_s[dst[e]]) keep_s[e] = 1;
    __syncthreads();

    // ---- budget (first BUDGET kept by index) + pack slots (serial)
    if (t == 0){
        int run = 0;
        for (int e = 0; e < En; e++){
            if (keep_s[e]){
                if (run < BUDGETn) run++;
                else keep_s[e] = 0;
            }
        }
        stats[b*10 + 1] = run;                   // Kb (for kept_ratio)
        int ka = 0, da = run;
        for (int e = 0; e < En; e++){
            if (keep_s[e]) slot_s[e] = (unsigned short)(ka++);
            else           slot_s[e] = (unsigned short)(da++);
        }
    }
    __syncthreads();

    // ---- write outputs (parallel)
    for (int e = t; e < En; e += 256){
        int slot = slot_s[e];
        int v = keep_s[e];
        out[b*2*En + slot]           = (float)src[e];
        out[b*2*En + En + slot]      = (float)dst[e];
        out[OFF_REL   + b*En + slot] = v ? (float)rel_s[e] : 0.0f;
        out[OFF_MASK  + b*En + slot] = v ? 1.0f : 0.0f;
        out[OFF_SCORE + b*En + slot] = v ? 1.0f : 0.0f;
    }
}

// ---------------- tail scalars ----------------------------------------------
__global__ void finalize_k(const int* __restrict__ stats, float* __restrict__ out){
    int t = threadIdx.x;
    if (t < 8){
        int s = 0;
        for (int b = 0; b < Bn; b++) s += stats[b*10 + 2 + t];
        out[OFF_TAIL + t] = (float)s / 32768.0f;
    } else if (t == 8){
        int s = 0;
        for (int b = 0; b < Bn; b++) s += stats[b*10 + 1];
        out[OFF_TAIL + 8] = (float)s / 32768.0f;
    } else if (t == 9){
        int s = 0;
        for (int b = 0; b < Bn; b++) s += stats[b*10 + 0];
        out[OFF_TAIL + 9] = 1.0f - (float)s / 32768.0f;
    }
}

// ------------------------------ launch --------------------------------------
extern "C" void kernel_launch(void* const* d_in, const int* in_sizes, int n_in,
                              void* d_out, int out_size)
{
    (void)in_sizes; (void)n_in; (void)out_size;
    const float* node_x  = (const float*)d_in[0];
    const int*   eidx    = (const int*)  d_in[1];
    const float* ebank   = (const float*)d_in[2];
    const float* commctx = (const float*)d_in[3];
    const float* W_node  = (const float*)d_in[4];
    const float* b_node  = (const float*)d_in[5];
    const float* W_edge  = (const float*)d_in[6];
    const float* b_edge  = (const float*)d_in[7];
    const float* W_comm  = (const float*)d_in[8];
    const float* b_comm  = (const float*)d_in[9];
    const float* ln_c_g  = (const float*)d_in[10];
    const float* ln_c_b  = (const float*)d_in[11];
    const float* W_clu   = (const float*)d_in[12];
    const float* b_clu   = (const float*)d_in[13];
    const float* W_tok   = (const float*)d_in[14];
    const float* b_tok   = (const float*)d_in[15];
    const float* W_r1    = (const float*)d_in[16];
    const float* b_r1    = (const float*)d_in[17];
    const float* ln_r_g  = (const float*)d_in[18];
    const float* ln_r_b  = (const float*)d_in[19];
    const float* W_r2    = (const float*)d_in[20];
    const float* b_r2    = (const float*)d_in[21];
    const float* hp      = (const float*)d_in[22];
    float* out = (float*)d_out;

    float *p_ef, *p_xn, *p_tok, *p_nodef, *p_commf, *p_p1, *p_p2, *p_zb;
    int *p_rel, *p_stats;
    cudaGetSymbolAddress((void**)&p_ef,    g_ef);
    cudaGetSymbolAddress((void**)&p_xn,    g_xn);
    cudaGetSymbolAddress((void**)&p_tok,   g_tok);
    cudaGetSymbolAddress((void**)&p_nodef, g_nodef);
    cudaGetSymbolAddress((void**)&p_commf, g_commf);
    cudaGetSymbolAddress((void**)&p_p1,    g_p1);
    cudaGetSymbolAddress((void**)&p_p2,    g_p2);
    cudaGetSymbolAddress((void**)&p_zb,    g_zerob);
    cudaGetSymbolAddress((void**)&p_rel,   g_rel);
    cudaGetSymbolAddress((void**)&p_stats, g_stats);

    dim3 blk(256);
    dim3 gSmall(2, 8);     // 1024 x 256
    dim3 gBig(2, 256);     // 32768 x 256

    // node_feat, comm_feat
    gemm_k<0><<<gSmall, blk>>>(node_x,  W_node, b_node, nullptr, p_nodef, 1024, 256, 256);
    gemm_k<0><<<gSmall, blk>>>(commctx, W_comm, b_comm, nullptr, p_commf, 1024, 256, 32);
    // factored src/dst tables: P1 = nodef @ W_tok[256:512], P2 = nodef @ W_tok[512:768]
    gemm_k<0><<<gSmall, blk>>>(p_nodef, W_tok + 256*256, p_zb, nullptr, p_p1, 1024, 256, 256);
    gemm_k<0><<<gSmall, blk>>>(p_nodef, W_tok + 512*256, p_zb, nullptr, p_p2, 1024, 256, 256);
    // edge_feat
    gemm_k<0><<<gBig, blk>>>(ebank, W_edge, b_edge, nullptr, p_ef, EG, 256, 16);
    // edge_feat2 = edge_feat + gelu(LN(edge_feat) @ W_clu + b_clu)
    ln_k<<<EG, blk>>>(p_ef, p_xn, ln_c_g, ln_c_b);
    gemm_k<2><<<gBig, blk>>>(p_xn, W_clu, b_clu, p_ef, p_ef, EG, 256, 256);
    // token = [ef2 | |cS-cD|] @ W_tok[{0:256,768:1024}] + P1[src] + P2[dst] + b_tok
    gemm_tok2_k<<<gBig, blk>>>(p_ef, p_commf, p_p1, p_p2, eidx, W_tok, b_tok, p_tok);
    // h = gelu(token @ W_r1 + b_r1)
    gemm_k<1><<<gBig, blk>>>(p_tok, W_r1, b_r1, nullptr, p_ef, EG, 256, 256);
    // h = LN(h)
    ln_k<<<EG, blk>>>(p_ef, p_xn, ln_r_g, ln_r_b);
    // routed = gelu(h @ W_r2 + b_r2)
    gemm_k<1><<<gBig, blk>>>(p_xn, W_r2, b_r2, nullptr, p_tok, EG, 256, 256);
    // relation_id
    logits2_k<<<EG*32/256, blk>>>(p_tok, hp, p_rel);
    // cap / guard / budget / pack + outputs
    route2_k<<<Bn, blk>>>(p_rel, eidx, out, p_stats);
    finalize_k<<<1, 32>>>(p_stats, out);
}

// round 17
// speedup vs baseline: 2.1926x; 1.8681x over previous
#include <cuda_runtime.h>
#include <cstdint>
#include <math.h>

#define Bn 4
#define Rn 256
#define En 8192
#define Dn 256
#define NEXPn 8
#define CAPn 1280
#define BUDGETn 7864
#define EG (Bn*En)
#define OFF_REL   65536
#define OFF_MASK  98304
#define OFF_SCORE 131072
#define OFF_TAIL  163840

typedef unsigned long long u64t;

// ------------- static device scratch (no allocations allowed) ---------------
__device__ float g_ef [EG*Dn];   // edge_feat -> edge_feat2 -> h
__device__ float g_xn [EG*Dn];   // LN outputs (reused)
__device__ float g_tok[EG*Dn];   // token -> routed (reused)
__device__ float g_nodef[Bn*Rn*Dn];
__device__ float g_commf[Bn*Rn*Dn];
__device__ float g_p1[Bn*Rn*Dn];     // nodef @ W_tok[256:512]
__device__ float g_p2[Bn*Rn*Dn];     // nodef @ W_tok[512:768]
__device__ float g_zerob[Dn];        // zero bias (zero-initialized)
__device__ int   g_rel[EG];
__device__ int   g_stats[Bn*10];

// ------------------------------- helpers ------------------------------------
__device__ __forceinline__ float gelu_f(float x){
    return 0.5f * x * (1.0f + erff(x * 0.7071067811865476f));
}
__device__ __forceinline__ uint32_t rotl32(uint32_t x, int d){
    return (x << d) | (x >> (32 - d));
}
// JAX threefry2x32 with key (0, 42)
__device__ __forceinline__ uint2 threefry2x32_k42(uint32_t x0, uint32_t x1){
    const uint32_t ks0 = 0u, ks1 = 42u;
    const uint32_t ks2 = ks0 ^ ks1 ^ 0x1BD11BDAu;
    const uint32_t ks[3] = {ks0, ks1, ks2};
    const int rotA[4] = {13,15,26,6};
    const int rotB[4] = {17,29,16,24};
    x0 += ks0; x1 += ks1;
    #pragma unroll
    for (int i = 0; i < 5; i++){
        #pragma unroll
        for (int j = 0; j < 4; j++){
            int rr = (i & 1) ? rotB[j] : rotA[j];
            x0 += x1; x1 = rotl32(x1, rr); x1 ^= x0;
        }
        x0 += ks[(i+1)%3];
        x1 += ks[(i+2)%3] + (uint32_t)(i+1);
    }
    return make_uint2(x0, x1);
}
// JAX partitionable threefry bits: counts (0, idx), out = out0 ^ out1
__device__ __forceinline__ uint32_t jax_bits(uint32_t idx){
    uint2 o2 = threefry2x32_k42(0u, idx);
    return o2.x ^ o2.y;
}

// ---- packed f32x2 FMA helpers (FFMA2 — PTX-only on sm_103a) ----------------
__device__ __forceinline__ u64t pk2(float lo, float hi){
    u64t r;
    asm("mov.b64 %0, {%1, %2};" : "=l"(r) : "f"(lo), "f"(hi));
    return r;
}
__device__ __forceinline__ void fma2(u64t &d, u64t a, u64t b){
    asm("fma.rn.f32x2 %0, %1, %2, %3;" : "=l"(d) : "l"(a), "l"(b), "l"(d));
}
__device__ __forceinline__ float2 upk2(u64t v){
    float2 f;
    asm("mov.b64 {%0, %1}, %2;" : "=f"(f.x), "=f"(f.y) : "l"(v));
    return f;
}

// --------- big fp32 GEMM (128x128 tile, FFMA2 + double-buffered smem) -------
// C = epi(A[MxK] @ B[KxN] + bias); EPI: 0 bias, 1 gelu, 2 addsrc+gelu
template<int EPI>
__global__ void __launch_bounds__(256, 2) gemm_k(
    const float* __restrict__ A, const float* __restrict__ Bm,
    const float* __restrict__ bias, const float* __restrict__ addsrc,
    float* __restrict__ C, int M, int N, int K)
{
    __shared__ float As[2][16][128];
    __shared__ float Bs[2][16][128];
    const int bn = blockIdx.x * 128;
    const int bm = blockIdx.y * 128;
    const int t  = threadIdx.x;
    const int tx = t & 15, ty = t >> 4;
    const int nk = K >> 4;

    u64t acc[8][4];
    #pragma unroll
    for (int i = 0; i < 8; i++)
        #pragma unroll
        for (int j = 0; j < 4; j++) acc[i][j] = 0ull;

    const int am0 = (t*2)     >> 2, ak0 = ((t*2)     & 3) * 4;
    const int am1 = (t*2 + 1) >> 2, ak1 = ((t*2 + 1) & 3) * 4;
    const int bk0 = (t*2)     >> 5, bn0 = ((t*2)     & 31) * 4;
    const int bk1 = (t*2 + 1) >> 5, bn1 = ((t*2 + 1) & 31) * 4;

    float4 ra0, ra1, rb0, rb1;
    ra0 = *reinterpret_cast<const float4*>(A + (size_t)(bm+am0)*K + ak0);
    ra1 = *reinterpret_cast<const float4*>(A + (size_t)(bm+am1)*K + ak1);
    rb0 = *reinterpret_cast<const float4*>(Bm + (size_t)bk0*N + bn + bn0);
    rb1 = *reinterpret_cast<const float4*>(Bm + (size_t)bk1*N + bn + bn1);
    As[0][ak0+0][am0] = ra0.x; As[0][ak0+1][am0] = ra0.y; As[0][ak0+2][am0] = ra0.z; As[0][ak0+3][am0] = ra0.w;
    As[0][ak1+0][am1] = ra1.x; As[0][ak1+1][am1] = ra1.y; As[0][ak1+2][am1] = ra1.z; As[0][ak1+3][am1] = ra1.w;
    *reinterpret_cast<float4*>(&Bs[0][bk0][bn0]) = rb0;
    *reinterpret_cast<float4*>(&Bs[0][bk1][bn1]) = rb1;
    __syncthreads();

    for (int it = 0; it < nk; it++){
        const int cur = it & 1;
        if (it + 1 < nk){
            int k0 = (it+1) << 4;
            ra0 = *reinterpret_cast<const float4*>(A + (size_t)(bm+am0)*K + k0 + ak0);
            ra1 = *reinterpret_cast<const float4*>(A + (size_t)(bm+am1)*K + k0 + ak1);
            rb0 = *reinterpret_cast<const float4*>(Bm + (size_t)(k0+bk0)*N + bn + bn0);
            rb1 = *reinterpret_cast<const float4*>(Bm + (size_t)(k0+bk1)*N + bn + bn1);
        }
        #pragma unroll
        for (int kk = 0; kk < 16; kk++){
            float a[8], b[8];
            *reinterpret_cast<float4*>(a)   = *reinterpret_cast<const float4*>(&As[cur][kk][ty*8]);
            *reinterpret_cast<float4*>(a+4) = *reinterpret_cast<const float4*>(&As[cur][kk][ty*8+4]);
            *reinterpret_cast<float4*>(b)   = *reinterpret_cast<const float4*>(&Bs[cur][kk][tx*8]);
            *reinterpret_cast<float4*>(b+4) = *reinterpret_cast<const float4*>(&Bs[cur][kk][tx*8+4]);
            u64t bp[4];
            #pragma unroll
            for (int j = 0; j < 4; j++) bp[j] = pk2(b[2*j], b[2*j+1]);
            #pragma unroll
            for (int i = 0; i < 8; i++){
                u64t ap = pk2(a[i], a[i]);
                #pragma unroll
                for (int j = 0; j < 4; j++) fma2(acc[i][j], ap, bp[j]);
            }
        }
        if (it + 1 < nk){
            const int nxt = cur ^ 1;
            As[nxt][ak0+0][am0] = ra0.x; As[nxt][ak0+1][am0] = ra0.y; As[nxt][ak0+2][am0] = ra0.z; As[nxt][ak0+3][am0] = ra0.w;
            As[nxt][ak1+0][am1] = ra1.x; As[nxt][ak1+1][am1] = ra1.y; As[nxt][ak1+2][am1] = ra1.z; As[nxt][ak1+3][am1] = ra1.w;
            *reinterpret_cast<float4*>(&Bs[nxt][bk0][bn0]) = rb0;
            *reinterpret_cast<float4*>(&Bs[nxt][bk1][bn1]) = rb1;
        }
        __syncthreads();
    }

    #pragma unroll
    for (int i = 0; i < 8; i++){
        int row = bm + ty*8 + i;
        #pragma unroll
        for (int j = 0; j < 4; j++){
            float2 vv = upk2(acc[i][j]);
            #pragma unroll
            for (int h = 0; h < 2; h++){
                int col = bn + tx*8 + 2*j + h;
                float v = (h ? vv.y : vv.x) + bias[col];
                if (EPI == 1) v = gelu_f(v);
                if (EPI == 2) v = addsrc[(size_t)row*N + col] + gelu_f(v);
                C[(size_t)row*N + col] = v;
            }
        }
    }
}

// --------- small-M GEMM (64x64 tile): more blocks for 1024-row GEMMs --------
__global__ void __launch_bounds__(256, 4) gemm64_k(
    const float* __restrict__ A, const float* __restrict__ Bm,
    const float* __restrict__ bias, float* __restrict__ C,
    int M, int N, int K)
{
    __shared__ float As[16][64];
    __shared__ float Bs[16][64];
    const int bn = blockIdx.x * 64;
    const int bm = blockIdx.y * 64;
    const int t  = threadIdx.x;
    const int tx = t & 15, ty = t >> 4;
    const int nk = K >> 4;

    u64t acc[4][2];
    #pragma unroll
    for (int i = 0; i < 4; i++){ acc[i][0] = 0ull; acc[i][1] = 0ull; }

    const int am = t >> 2, akk = (t & 3) * 4;      // A: 64 rows x 16 k
    const int bkk = t >> 4, bn4 = (t & 15) * 4;    // B: 16 k x 64 cols

    for (int it = 0; it < nk; it++){
        int k0 = it << 4;
        float4 va = *reinterpret_cast<const float4*>(A + (size_t)(bm+am)*K + k0 + akk);
        As[akk+0][am] = va.x; As[akk+1][am] = va.y; As[akk+2][am] = va.z; As[akk+3][am] = va.w;
        *reinterpret_cast<float4*>(&Bs[bkk][bn4]) =
            *reinterpret_cast<const float4*>(Bm + (size_t)(k0+bkk)*N + bn + bn4);
        __syncthreads();
        #pragma unroll
        for (int kk = 0; kk < 16; kk++){
            float a[4], b[4];
            *reinterpret_cast<float4*>(a) = *reinterpret_cast<const float4*>(&As[kk][ty*4]);
            *reinterpret_cast<float4*>(b) = *reinterpret_cast<const float4*>(&Bs[kk][tx*4]);
            u64t bp0 = pk2(b[0], b[1]);
            u64t bp1 = pk2(b[2], b[3]);
            #pragma unroll
            for (int i = 0; i < 4; i++){
                u64t ap = pk2(a[i], a[i]);
                fma2(acc[i][0], ap, bp0);
                fma2(acc[i][1], ap, bp1);
            }
        }
        __syncthreads();
    }

    #pragma unroll
    for (int i = 0; i < 4; i++){
        int row = bm + ty*4 + i;
        #pragma unroll
        for (int j = 0; j < 2; j++){
            float2 vv = upk2(acc[i][j]);
            int col = bn + tx*4 + 2*j;
            C[(size_t)row*N + col]     = vv.x + bias[col];
            C[(size_t)row*N + col + 1] = vv.y + bias[col + 1];
        }
    }
}

// ---- factored token GEMM (K=512): token = [ef2 | |cS-cD|] @ W_tok[{0:256,768:1024}]
//      + P1[src] + P2[dst] + bias
__global__ void __launch_bounds__(256, 2) gemm_tok2_k(
    const float* __restrict__ ef2, const float* __restrict__ commf,
    const float* __restrict__ P1, const float* __restrict__ P2,
    const int* __restrict__ eidx,
    const float* __restrict__ Wtok, const float* __restrict__ bias,
    float* __restrict__ C)
{
    __shared__ float As[2][16][128];
    __shared__ float Bs[2][16][128];
    __shared__ int s_s[128], d_s[128];
    const int bn = blockIdx.x * 128;
    const int bm = blockIdx.y * 128;
    const int t  = threadIdx.x;
    const int tx = t & 15, ty = t >> 4;
    const int bidx = bm >> 13;
    const int nb   = bidx << 8;

    if (t < 128){
        int ei = (bm & (En-1)) + t;
        s_s[t] = eidx[bidx*2*En + ei];
        d_s[t] = eidx[bidx*2*En + En + ei];
    }
    u64t acc[8][4];
    #pragma unroll
    for (int i = 0; i < 8; i++)
        #pragma unroll
        for (int j = 0; j < 4; j++) acc[i][j] = 0ull;

    const int am0 = (t*2)     >> 2, ak0 = ((t*2)     & 3) * 4;
    const int am1 = (t*2 + 1) >> 2, ak1 = ((t*2 + 1) & 3) * 4;
    const int bk0 = (t*2)     >> 5, bn0 = ((t*2)     & 31) * 4;
    const int bk1 = (t*2 + 1) >> 5, bn1 = ((t*2 + 1) & 31) * 4;
    __syncthreads();

    auto loadA = [&](int k0, int m, int kk) -> float4 {
        int e = bm + m;
        if (k0 < 256){
            return *reinterpret_cast<const float4*>(ef2 + (size_t)e*256 + k0 + kk);
        } else {
            int off = k0 - 256 + kk;
            float4 a4 = *reinterpret_cast<const float4*>(commf + (size_t)(nb + s_s[m])*256 + off);
            float4 c4 = *reinterpret_cast<const float4*>(commf + (size_t)(nb + d_s[m])*256 + off);
            return make_float4(fabsf(a4.x-c4.x), fabsf(a4.y-c4.y),
                               fabsf(a4.z-c4.z), fabsf(a4.w-c4.w));
        }
    };
    auto wrow = [&](int k) -> size_t {
        return (size_t)(k < 256 ? k : k + 512) * 256;
    };

    float4 ra0, ra1, rb0, rb1;
    ra0 = loadA(0, am0, ak0);
    ra1 = loadA(0, am1, ak1);
    rb0 = *reinterpret_cast<const float4*>(Wtok + wrow(bk0) + bn + bn0);
    rb1 = *reinterpret_cast<const float4*>(Wtok + wrow(bk1) + bn + bn1);
    As[0][ak0+0][am0] = ra0.x; As[0][ak0+1][am0] = ra0.y; As[0][ak0+2][am0] = ra0.z; As[0][ak0+3][am0] = ra0.w;
    As[0][ak1+0][am1] = ra1.x; As[0][ak1+1][am1] = ra1.y; As[0][ak1+2][am1] = ra1.z; As[0][ak1+3][am1] = ra1.w;
    *reinterpret_cast<float4*>(&Bs[0][bk0][bn0]) = rb0;
    *reinterpret_cast<float4*>(&Bs[0][bk1][bn1]) = rb1;
    __syncthreads();

    const int nk = 512 >> 4;
    for (int it = 0; it < nk; it++){
        const int cur = it & 1;
        if (it + 1 < nk){
            int k0 = (it+1) << 4;
            ra0 = loadA(k0, am0, ak0);
            ra1 = loadA(k0, am1, ak1);
            rb0 = *reinterpret_cast<const float4*>(Wtok + wrow(k0+bk0) + bn + bn0);
            rb1 = *reinterpret_cast<const float4*>(Wtok + wrow(k0+bk1) + bn + bn1);
        }
        #pragma unroll
        for (int kk = 0; kk < 16; kk++){
            float a[8], b[8];
            *reinterpret_cast<float4*>(a)   = *reinterpret_cast<const float4*>(&As[cur][kk][ty*8]);
            *reinterpret_cast<float4*>(a+4) = *reinterpret_cast<const float4*>(&As[cur][kk][ty*8+4]);
            *reinterpret_cast<float4*>(b)   = *reinterpret_cast<const float4*>(&Bs[cur][kk][tx*8]);
            *reinterpret_cast<float4*>(b+4) = *reinterpret_cast<const float4*>(&Bs[cur][kk][tx*8+4]);
            u64t bp[4];
            #pragma unroll
            for (int j = 0; j < 4; j++) bp[j] = pk2(b[2*j], b[2*j+1]);
            #pragma unroll
            for (int i = 0; i < 8; i++){
                u64t ap = pk2(a[i], a[i]);
                #pragma unroll
                for (int j = 0; j < 4; j++) fma2(acc[i][j], ap, bp[j]);
            }
        }
        if (it + 1 < nk){
            const int nxt = cur ^ 1;
            As[nxt][ak0+0][am0] = ra0.x; As[nxt][ak0+1][am0] = ra0.y; As[nxt][ak0+2][am0] = ra0.z; As[nxt][ak0+3][am0] = ra0.w;
            As[nxt][ak1+0][am1] = ra1.x; As[nxt][ak1+1][am1] = ra1.y; As[nxt][ak1+2][am1] = ra1.z; As[nxt][ak1+3][am1] = ra1.w;
            *reinterpret_cast<float4*>(&Bs[nxt][bk0][bn0]) = rb0;
            *reinterpret_cast<float4*>(&Bs[nxt][bk1][bn1]) = rb1;
        }
        __syncthreads();
    }

    #pragma unroll
    for (int i = 0; i < 8; i++){
        int mrow = ty*8 + i;
        int row = bm + mrow;
        const float* p1r = P1 + (size_t)(nb + s_s[mrow])*256;
        const float* p2r = P2 + (size_t)(nb + d_s[mrow])*256;
        #pragma unroll
        for (int j = 0; j < 4; j++){
            float2 vv = upk2(acc[i][j]);
            int col = bn + tx*8 + 2*j;
            float2 q1 = *reinterpret_cast<const float2*>(p1r + col);
            float2 q2 = *reinterpret_cast<const float2*>(p2r + col);
            C[(size_t)row*256 + col]     = vv.x + bias[col]     + q1.x + q2.x;
            C[(size_t)row*256 + col + 1] = vv.y + bias[col + 1] + q1.y + q2.y;
        }
    }
}

// ---------------- LayerNorm over last dim (256), one block per row ----------
__global__ void __launch_bounds__(256) ln_k(
    const float* __restrict__ x, float* __restrict__ y,
    const float* __restrict__ g, const float* __restrict__ bb)
{
    const int row = blockIdx.x, t = threadIdx.x;
    __shared__ float red[8];
    float v = x[(size_t)row*256 + t];
    float s = v;
    #pragma unroll
    for (int o = 16; o; o >>= 1) s += __shfl_xor_sync(0xffffffffu, s, o);
    if ((t & 31) == 0) red[t >> 5] = s;
    __syncthreads();
    float tot = 0.0f;
    #pragma unroll
    for (int i = 0; i < 8; i++) tot += red[i];
    float mu = tot * (1.0f/256.0f);
    float d = v - mu;
    __syncthreads();
    float s2 = d * d;
    #pragma unroll
    for (int o = 16; o; o >>= 1) s2 += __shfl_xor_sync(0xffffffffu, s2, o);
    if ((t & 31) == 0) red[t >> 5] = s2;
    __syncthreads();
    float tot2 = 0.0f;
    #pragma unroll
    for (int i = 0; i < 8; i++) tot2 += red[i];
    float var = tot2 * (1.0f/256.0f);
    y[(size_t)row*256 + t] = d * rsqrtf(var + 1e-5f) * g[t] + bb[t];
}

// ------- logits + parallel Gumbel (lanes 0-7) + shfl argmax -----------------
__global__ void __launch_bounds__(256) logits_k(
    const float* __restrict__ routed, const float* __restrict__ hp,
    int* __restrict__ relout)
{
    const int gw = (blockIdx.x * 256 + threadIdx.x) >> 5;   // one warp per edge
    const int lane = threadIdx.x & 31;
    const float* r = routed + (size_t)gw * 256;
    float x[8];
    #pragma unroll
    for (int i = 0; i < 8; i++) x[i] = r[lane + 32*i];
    float myl = 0.0f;
    #pragma unroll
    for (int m = 0; m < 8; m++){
        const float* h = hp + m*256;
        float p = 0.0f;
        #pragma unroll
        for (int i = 0; i < 8; i++) p = fmaf(x[i], h[lane + 32*i], p);
        #pragma unroll
        for (int o = 16; o; o >>= 1) p += __shfl_xor_sync(0xffffffffu, p, o);
        if (lane == m) myl = p;
    }
    float z = -INFINITY;
    if (lane < 8){
        uint32_t bits = jax_bits((uint32_t)gw * 8u + (uint32_t)lane);
        float f = __uint_as_float((bits >> 9) | 0x3f800000u) - 1.0f;
        const float lo = 1e-6f;
        const float span = (1.0f - 1e-6f) - 1e-6f;
        float u = fmaxf(lo, __fadd_rn(__fmul_rn(f, span), lo));
        z = myl - logf(-logf(u));
    }
    float bz = z; int bi = lane;
    #pragma unroll
    for (int o = 4; o; o >>= 1){
        float oz = __shfl_down_sync(0xffffffffu, bz, o);
        int   oi = __shfl_down_sync(0xffffffffu, bi, o);
        if (oz > bz || (oz == bz && oi < bi)){ bz = oz; bi = oi; }
    }
    if (lane == 0) relout[gw] = bi;
}

// ------- routing tail: parallel cap (match_any) / guard / budget / pack -----
__global__ void __launch_bounds__(256) route_k(
    const int* __restrict__ relg, const int* __restrict__ eidx,
    float* __restrict__ out, int* __restrict__ stats)
{
    const int b = blockIdx.x;
    const int t = threadIdx.x;
    const int lane = t & 31, w = t >> 5;
    __shared__ unsigned char rel_s[En];
    __shared__ unsigned char keep_s[En];
    __shared__ unsigned char cov_s[Rn];
    __shared__ int base[8];
    __shared__ int whist[8][8];
    __shared__ int wsum[8];
    __shared__ int runbase;
    __shared__ int Kb_s;
    const int* src = eidx + b*2*En;
    const int* dst = src + En;

    for (int e = t; e < En; e += 256) rel_s[e] = (unsigned char)relg[b*En + e];
    if (t < 8) base[t] = 0;
    if (t < Rn) cov_s[t] = 0;
    __syncthreads();

    // ---- capacity: rank within relation (index order) < CAP ----
    for (int c = 0; c < En/256; c++){
        if (t < 64) ((int*)whist)[t] = 0;
        __syncthreads();
        int e = c*256 + t;
        int r = rel_s[e];
        unsigned mm = __match_any_sync(0xffffffffu, r);
        int before = __popc(mm & ((1u << lane) - 1u));
        if (before == 0) whist[w][r] = __popc(mm);
        __syncthreads();
        int pre = 0;
        #pragma unroll
        for (int ww = 0; ww < 8; ww++) if (ww < w) pre += whist[ww][r];
        int rank = base[r] + pre + before;
        keep_s[e] = (rank < CAPn) ? 1 : 0;
        __syncthreads();
        if (t < 8){
            int s = 0;
            #pragma unroll
            for (int ww = 0; ww < 8; ww++) s += whist[ww][t];
            base[t] += s;
        }
        __syncthreads();
    }
    // kept-after-cap count + relation histogram
    {
        int myk = 0;
        for (int e = t; e < En; e += 256) myk += keep_s[e];
        #pragma unroll
        for (int o = 16; o; o >>= 1) myk += __shfl_xor_sync(0xffffffffu, myk, o);
        if (lane == 0) wsum[w] = myk;
        __syncthreads();
        if (t == 0){
            int s = 0;
            for (int i = 0; i < 8; i++) s += wsum[i];
            stats[b*10 + 0] = s;
        }
        if (t < 8) stats[b*10 + 2 + t] = base[t];
        __syncthreads();
    }

    // ---- guard: add every edge touching an uncovered node ----
    for (int e = t; e < En; e += 256)
        if (keep_s[e]){ cov_s[src[e]] = 1; cov_s[dst[e]] = 1; }
    __syncthreads();
    for (int e = t; e < En; e += 256)
        if (!cov_s[src[e]] || !cov_s[dst[e]]) keep_s[e] = 1;
    __syncthreads();

    // ---- budget: keep first BUDGET kept by index ----
    if (t == 0) runbase = 0;
    __syncthreads();
    for (int c = 0; c < En/256; c++){
        int e = c*256 + t;
        int v = keep_s[e];
        int x = v;
        #pragma unroll
        for (int o = 1; o < 32; o <<= 1){
            int y = __shfl_up_sync(0xffffffffu, x, o);
            if (lane >= o) x += y;
        }
        if (lane == 31) wsum[w] = x;
        __syncthreads();
        int wpre = 0;
        #pragma unroll
        for (int ww = 0; ww < 8; ww++) if (ww < w) wpre += wsum[ww];
        int excl = runbase + wpre + x - v;
        keep_s[e] = (v && (excl < BUDGETn)) ? 1 : 0;
        __syncthreads();
        if (t == 0){
            int s = 0;
            for (int i = 0; i < 8; i++) s += wsum[i];
            runbase += s;
        }
        __syncthreads();
    }
    if (t == 0){
        Kb_s = runbase < BUDGETn ? runbase : BUDGETn;
        stats[b*10 + 1] = Kb_s;
        runbase = 0;
    }
    __syncthreads();
    const int Kb = Kb_s;

    // ---- pack: stable partition, write outputs ----
    for (int c = 0; c < En/256; c++){
        int e = c*256 + t;
        int v = keep_s[e];
        int x = v;
        #pragma unroll
        for (int o = 1; o < 32; o <<= 1){
            int y = __shfl_up_sync(0xffffffffu, x, o);
            if (lane >= o) x += y;
        }
        if (lane == 31) wsum[w] = x;
        __syncthreads();
        int wpre = 0;
        #pragma unroll
        for (int ww = 0; ww < 8; ww++) if (ww < w) wpre += wsum[ww];
        int excl = runbase + wpre + x - v;        // kept in [0,e)
        int slot = v ? excl : (Kb + (e - excl));  // dropped after all kept
        out[b*2*En + slot]           = (float)src[e];
        out[b*2*En + En + slot]      = (float)dst[e];
        out[OFF_REL   + b*En + slot] = v ? (float)rel_s[e] : 0.0f;
        out[OFF_MASK  + b*En + slot] = v ? 1.0f : 0.0f;
        out[OFF_SCORE + b*En + slot] = v ? 1.0f : 0.0f;
        __syncthreads();
        if (t == 0){
            int s = 0;
            for (int i = 0; i < 8; i++) s += wsum[i];
            runbase += s;
        }
        __syncthreads();
    }
}

// ---------------- tail scalars ----------------------------------------------
__global__ void finalize_k(const int* __restrict__ stats, float* __restrict__ out){
    int t = threadIdx.x;
    if (t < 8){
        int s = 0;
        for (int b = 0; b < Bn; b++) s += stats[b*10 + 2 + t];
        out[OFF_TAIL + t] = (float)s / 32768.0f;
    } else if (t == 8){
        int s = 0;
        for (int b = 0; b < Bn; b++) s += stats[b*10 + 1];
        out[OFF_TAIL + 8] = (float)s / 32768.0f;
    } else if (t == 9){
        int s = 0;
        for (int b = 0; b < Bn; b++) s += stats[b*10 + 0];
        out[OFF_TAIL + 9] = 1.0f - (float)s / 32768.0f;
    }
}

// ------------------------------ launch --------------------------------------
extern "C" void kernel_launch(void* const* d_in, const int* in_sizes, int n_in,
                              void* d_out, int out_size)
{
    (void)in_sizes; (void)n_in; (void)out_size;
    const float* node_x  = (const float*)d_in[0];
    const int*   eidx    = (const int*)  d_in[1];
    const float* ebank   = (const float*)d_in[2];
    const float* commctx = (const float*)d_in[3];
    const float* W_node  = (const float*)d_in[4];
    const float* b_node  = (const float*)d_in[5];
    const float* W_edge  = (const float*)d_in[6];
    const float* b_edge  = (const float*)d_in[7];
    const float* W_comm  = (const float*)d_in[8];
    const float* b_comm  = (const float*)d_in[9];
    const float* ln_c_g  = (const float*)d_in[10];
    const float* ln_c_b  = (const float*)d_in[11];
    const float* W_clu   = (const float*)d_in[12];
    const float* b_clu   = (const float*)d_in[13];
    const float* W_tok   = (const float*)d_in[14];
    const float* b_tok   = (const float*)d_in[15];
    const float* W_r1    = (const float*)d_in[16];
    const float* b_r1    = (const float*)d_in[17];
    const float* ln_r_g  = (const float*)d_in[18];
    const float* ln_r_b  = (const float*)d_in[19];
    const float* W_r2    = (const float*)d_in[20];
    const float* b_r2    = (const float*)d_in[21];
    const float* hp      = (const float*)d_in[22];
    float* out = (float*)d_out;

    float *p_ef, *p_xn, *p_tok, *p_nodef, *p_commf, *p_p1, *p_p2, *p_zb;
    int *p_rel, *p_stats;
    cudaGetSymbolAddress((void**)&p_ef,    g_ef);
    cudaGetSymbolAddress((void**)&p_xn,    g_xn);
    cudaGetSymbolAddress((void**)&p_tok,   g_tok);
    cudaGetSymbolAddress((void**)&p_nodef, g_nodef);
    cudaGetSymbolAddress((void**)&p_commf, g_commf);
    cudaGetSymbolAddress((void**)&p_p1,    g_p1);
    cudaGetSymbolAddress((void**)&p_p2,    g_p2);
    cudaGetSymbolAddress((void**)&p_zb,    g_zerob);
    cudaGetSymbolAddress((void**)&p_rel,   g_rel);
    cudaGetSymbolAddress((void**)&p_stats, g_stats);

    dim3 blk(256);
    dim3 gS64(4, 16);      // 1024 x 256 with 64x64 tiles
    dim3 gBig(2, 256);     // 32768 x 256 with 128x128 tiles

    // node_feat, comm_feat (64x64-tile kernels: 64 blocks each)
    gemm64_k<<<gS64, blk>>>(node_x,  W_node, b_node, p_nodef, 1024, 256, 256);
    gemm64_k<<<gS64, blk>>>(commctx, W_comm, b_comm, p_commf, 1024, 256, 32);
    // factored src/dst tables
    gemm64_k<<<gS64, blk>>>(p_nodef, W_tok + 256*256, p_zb, p_p1, 1024, 256, 256);
    gemm64_k<<<gS64, blk>>>(p_nodef, W_tok + 512*256, p_zb, p_p2, 1024, 256, 256);
    // edge_feat
    gemm_k<0><<<gBig, blk>>>(ebank, W_edge, b_edge, nullptr, p_ef, EG, 256, 16);
    // edge_feat2 = edge_feat + gelu(LN(edge_feat) @ W_clu + b_clu)
    ln_k<<<EG, blk>>>(p_ef, p_xn, ln_c_g, ln_c_b);
    gemm_k<2><<<gBig, blk>>>(p_xn, W_clu, b_clu, p_ef, p_ef, EG, 256, 256);
    // token = [ef2 | |cS-cD|] @ W_tok[{0:256,768:1024}] + P1[src] + P2[dst] + b_tok
    gemm_tok2_k<<<gBig, blk>>>(p_ef, p_commf, p_p1, p_p2, eidx, W_tok, b_tok, p_tok);
    // h = gelu(token @ W_r1 + b_r1)
    gemm_k<1><<<gBig, blk>>>(p_tok, W_r1, b_r1, nullptr, p_ef, EG, 256, 256);
    // h = LN(h)
    ln_k<<<EG, blk>>>(p_ef, p_xn, ln_r_g, ln_r_b);
    // routed = gelu(h @ W_r2 + b_r2)
    gemm_k<1><<<gBig, blk>>>(p_xn, W_r2, b_r2, nullptr, p_tok, EG, 256, 256);
    // relation_id (parallel gumbel/argmax)
    logits_k<<<EG*32/256, blk>>>(p_tok, hp, p_rel);
    // cap / guard / budget / pack + outputs (parallel)
    route_k<<<Bn, blk>>>(p_rel, eidx, out, p_stats);
    finalize_k<<<1, 32>>>(p_stats, out);
}